// round 10
// baseline (speedup 1.0000x reference)
#include <cuda_runtime.h>
#include <math.h>

#define B_ 64
#define S_ 512
#define I_ 256
#define H_ 1024
#define O_ 256

__device__ float g_buf0[S_ * B_ * H_];
__device__ float g_buf1[S_ * B_ * H_];
// Pre-swizzled weight blob: [mat(3: W0hh,W1ih,W1hh)][ng(32)][k(1024)][32]
__device__ float g_wblob[3 * 32 * 1024 * 32];
// flags0 then flags1: [t(512)][bg(4)][chunk(4)], target 128 (8 CTAs x 16 warps)
__device__ int g_flags[2 * S_ * 16];

typedef unsigned long long u64;

__device__ __forceinline__ u64 pack2(float x, float y) {
    u64 r; asm("mov.b64 %0,{%1,%2};" : "=l"(r) : "f"(x), "f"(y)); return r;
}
__device__ __forceinline__ u64 fma2(u64 a, u64 b, u64 c) {
    u64 d; asm("fma.rn.f32x2 %0,%1,%2,%3;" : "=l"(d) : "l"(a), "l"(b), "l"(c)); return d;
}
__device__ __forceinline__ u64 add2(u64 a, u64 b) {
    u64 d; asm("add.rn.f32x2 %0,%1,%2;" : "=l"(d) : "l"(a), "l"(b)); return d;
}
__device__ __forceinline__ float2 unpk(u64 v) {
    float2 f; asm("mov.b64 {%0,%1},%2;" : "=f"(f.x), "=f"(f.y) : "l"(v)); return f;
}
__device__ __forceinline__ void cpasync16(float* sdst, const float* gsrc) {
    unsigned sa = (unsigned)__cvta_generic_to_shared(sdst);
    asm volatile("cp.async.cg.shared.global [%0], [%1], 16;" :: "r"(sa), "l"(gsrc));
}
__device__ __forceinline__ int ld_acq(const int* p) {
    int v; asm volatile("ld.acquire.gpu.global.b32 %0, [%1];" : "=r"(v) : "l"(p) : "memory");
    return v;
}
__device__ __forceinline__ void red_release(int* p) {
    asm volatile("red.release.gpu.global.add.s32 [%0], 1;" :: "l"(p) : "memory");
}

__global__ void zero_flags_k(int* f) { f[blockIdx.x * 1024 + threadIdx.x] = 0; }

// Transpose+swizzle weights into blob. block=(kt, ng, m), 256 thr.
__global__ void __launch_bounds__(256) wprep_k(const float* __restrict__ W0hh,
                                               const float* __restrict__ W1ih,
                                               const float* __restrict__ W1hh,
                                               float* __restrict__ blob) {
    __shared__ float s[32][33];
    const int kt = blockIdx.x, ng = blockIdx.y, m = blockIdx.z;
    const float* W = (m == 0) ? W0hh : (m == 1) ? W1ih : W1hh;
    const int tid = threadIdx.x;
#pragma unroll
    for (int it = 0; it < 4; it++) {
        int idx = tid + it * 256;
        int j = idx >> 5, kk = idx & 31;
        s[j][kk] = W[(size_t)(ng * 32 + j) * H_ + kt * 32 + kk];
    }
    __syncthreads();
#pragma unroll
    for (int it = 0; it < 4; it++) {
        int idx = tid + it * 256;
        int kk = idx >> 5, j = idx & 31;
        int k = kt * 32 + kk;
        int sw = (((j >> 2) ^ ((k >> 2) & 7)) << 2) | (j & 3);
        blob[((size_t)(m * 32 + ng) * 1024 + k) * 32 + sw] = s[j][kk];
    }
}

// ---------------------------------------------------------------------------
// Tiled fp32 GEMM (unchanged) — pre0 and fc only.
// ---------------------------------------------------------------------------
template <int K, int AROW, int CROW>
__global__ void __launch_bounds__(128) gemm_k(const float* __restrict__ A,
                                              const float* __restrict__ W,
                                              const float* __restrict__ b1,
                                              const float* __restrict__ b2,
                                              float* __restrict__ C) {
    __shared__ __align__(16) float sA[32][68];
    __shared__ __align__(16) float sB[32][132];
    const int s = blockIdx.y, n0 = blockIdx.x * 128, tid = threadIdx.x;
    const int tm = tid & 7, tn = tid >> 3;
    u64 acc[8][4];
#pragma unroll
    for (int i = 0; i < 8; i++)
#pragma unroll
        for (int j = 0; j < 4; j++) acc[i][j] = 0ull;
    for (int kc = 0; kc < K; kc += 32) {
#pragma unroll
        for (int i = 0; i < 4; i++) {
            int v = tid + i * 128, b = v >> 3, kq = v & 7;
            size_t row = AROW ? ((size_t)s * B_ + b) : ((size_t)b * S_ + s);
            float4 f = __ldg((const float4*)(A + row * K + kc + kq * 4));
            sA[kq * 4 + 0][b] = f.x; sA[kq * 4 + 1][b] = f.y;
            sA[kq * 4 + 2][b] = f.z; sA[kq * 4 + 3][b] = f.w;
        }
#pragma unroll
        for (int i = 0; i < 8; i++) {
            int v = tid + i * 128, n = v >> 3, kq = v & 7;
            float4 f = __ldg((const float4*)(W + (size_t)(n0 + n) * K + kc + kq * 4));
            sB[kq * 4 + 0][n] = f.x; sB[kq * 4 + 1][n] = f.y;
            sB[kq * 4 + 2][n] = f.z; sB[kq * 4 + 3][n] = f.w;
        }
        __syncthreads();
#pragma unroll
        for (int k = 0; k < 32; k++) {
            float4 a0 = *(const float4*)&sA[k][tm * 8];
            float4 a1 = *(const float4*)&sA[k][tm * 8 + 4];
            ulonglong2 w01 = *(const ulonglong2*)&sB[k][tn * 8];
            ulonglong2 w23 = *(const ulonglong2*)&sB[k][tn * 8 + 4];
            float av[8] = {a0.x, a0.y, a0.z, a0.w, a1.x, a1.y, a1.z, a1.w};
#pragma unroll
            for (int i = 0; i < 8; i++) {
                u64 ai = pack2(av[i], av[i]);
                acc[i][0] = fma2(ai, w01.x, acc[i][0]);
                acc[i][1] = fma2(ai, w01.y, acc[i][1]);
                acc[i][2] = fma2(ai, w23.x, acc[i][2]);
                acc[i][3] = fma2(ai, w23.y, acc[i][3]);
            }
        }
        __syncthreads();
    }
    float bias[8];
#pragma unroll
    for (int j8 = 0; j8 < 8; j8++) {
        int n = n0 + tn * 8 + j8;
        bias[j8] = b1[n] + (b2 ? b2[n] : 0.0f);
    }
    const int NC = CROW ? O_ : H_;
#pragma unroll
    for (int i = 0; i < 8; i++) {
        int b = tm * 8 + i;
        size_t row = CROW ? ((size_t)b * S_ + s) : ((size_t)s * B_ + b);
        float* Co = C + row * NC + n0 + tn * 8;
        float2 t0 = unpk(acc[i][0]), t1 = unpk(acc[i][1]);
        float2 t2 = unpk(acc[i][2]), t3 = unpk(acc[i][3]);
        *(float4*)Co       = make_float4(t0.x + bias[0], t0.y + bias[1],
                                         t1.x + bias[2], t1.y + bias[3]);
        *(float4*)(Co + 4) = make_float4(t2.x + bias[4], t2.y + bias[5],
                                         t3.x + bias[6], t3.y + bias[7]);
    }
}

// ---------------------------------------------------------------------------
// Fused 2-layer RNN. Iter t (1..513): L0 step t (t<512), pre1 matvec for
// t-1 (t<=512), L1 step t-2 (t>=2). Weights streamed from blob in 8KB
// double-buffered chunks per quad (12 chunks/iter: m0 c0..3, m1, m2).
// ---------------------------------------------------------------------------
#define SH_ROW 1028
#define SHF    (16 * SH_ROW)   // 16448 f per h stage

__global__ void __launch_bounds__(512) fused_k(const float* __restrict__ blob,
                                               const float* __restrict__ bi1,
                                               const float* __restrict__ bh1,
                                               float* __restrict__ buf0,
                                               float* __restrict__ buf1,
                                               int* __restrict__ flags) {
    extern __shared__ __align__(16) float smem[];
    float* sH0 = smem;                       // [16][1028]
    float* sH1 = smem + SHF;                 // [16][1028]
    float* sWS = smem + 2 * SHF;             // [4 quads][2][2048]
    u64* redL0 = (u64*)(sWS + 16384);        // 1024 u64 each
    u64* redP1 = redL0 + 1024;
    u64* redL1 = redP1 + 1024;
    float* sPre = (float*)(redL1 + 1024);    // [16][32]

    const int tid = threadIdx.x;
    const int warp = tid >> 5, lane = tid & 31;
    const int ng4 = warp & 3, kg = warp >> 2;
    const int ks = lane & 7, q = lane >> 3;
    const int bg = blockIdx.x & 3, ng = blockIdx.x >> 2;
    const int n0 = ng * 32, b0 = bg * 16;
    const int ca = (((ng4 * 2) ^ ks) << 2), cb = ca ^ 4;
    const int mychunk = ng >> 3;
    const int gtid = tid & 127;
    int* flags0 = flags;
    int* flags1 = flags + S_ * 16;

    u64 biasv = 0, pregOld = 0, pregNew = 0;
    if (lane < 16) {
        int n = n0 + lane * 2;
        biasv = pack2(bi1[n] + bh1[n], bi1[n + 1] + bh1[n + 1]);
    }

    // t=0: h0_0 = tanh(pre0_0)
    if (lane < 16) {
        float* a = buf0 + ((size_t)(b0 + warp)) * H_ + n0 + lane * 2;
        float2 v = unpk(*(const u64*)a);
        *(u64*)a = pack2(tanhf(v.x), tanhf(v.y));
    }
    __syncwarp();
    if (lane == 0) red_release(&flags0[0 * 16 + bg * 4 + mychunk]);
    __syncthreads();

    const float* h0b = sH0 + q * SH_ROW + kg * 256 + ks * 4;
    const float* h1b = sH1 + q * SH_ROW + kg * 256 + ks * 4;

#define QUADBAR() asm volatile("bar.sync %0, 128;" :: "r"(1 + kg) : "memory")
#define COMMIT()  asm volatile("cp.async.commit_group;")
#define STREAM_CHUNK(J)                                                        \
    { const float* src_ = blob + ((size_t)(((J) >> 2) * 32 + ng) * 1024        \
                                  + kg * 256 + ((J) & 3) * 64) * 32;           \
      float* dst_ = sWS + kg * 4096 + ((J) & 1) * 2048;                        \
      _Pragma("unroll") for (int i_ = 0; i_ < 4; i_++)                         \
          cpasync16(dst_ + (gtid + i_ * 128) * 4, src_ + (gtid + i_ * 128) * 4); }
#define DO_KK(KK, CMP)                                                         \
    { ulonglong2 wa = *(const ulonglong2*)(wr + KK * 32 + ca);                 \
      ulonglong2 wb = *(const ulonglong2*)(wr + KK * 32 + cb);                 \
      u64 p0 = pack2(h0v.CMP, h0v.CMP); u64 p1 = pack2(h1v.CMP, h1v.CMP);      \
      u64 p2 = pack2(h2v.CMP, h2v.CMP); u64 p3 = pack2(h3v.CMP, h3v.CMP);      \
      acc[0][0] = fma2(p0, wa.x, acc[0][0]); acc[0][1] = fma2(p0, wa.y, acc[0][1]); \
      acc[0][2] = fma2(p0, wb.x, acc[0][2]); acc[0][3] = fma2(p0, wb.y, acc[0][3]); \
      acc[1][0] = fma2(p1, wa.x, acc[1][0]); acc[1][1] = fma2(p1, wa.y, acc[1][1]); \
      acc[1][2] = fma2(p1, wb.x, acc[1][2]); acc[1][3] = fma2(p1, wb.y, acc[1][3]); \
      acc[2][0] = fma2(p2, wa.x, acc[2][0]); acc[2][1] = fma2(p2, wa.y, acc[2][1]); \
      acc[2][2] = fma2(p2, wb.x, acc[2][2]); acc[2][3] = fma2(p2, wb.y, acc[2][3]); \
      acc[3][0] = fma2(p3, wa.x, acc[3][0]); acc[3][1] = fma2(p3, wa.y, acc[3][1]); \
      acc[3][2] = fma2(p3, wb.x, acc[3][2]); acc[3][3] = fma2(p3, wb.y, acc[3][3]); }
#define MATVEC(MB, HB, RED)                                                    \
    { u64 acc[4][4];                                                           \
      _Pragma("unroll") for (int i = 0; i < 4; i++)                            \
          _Pragma("unroll") for (int j2 = 0; j2 < 4; j2++) acc[i][j2] = 0ull;  \
      _Pragma("unroll")                                                        \
      for (int c = 0; c < 4; c++) {                                            \
          const int j = (MB) * 4 + c;                                          \
          if (j <= 10) asm volatile("cp.async.wait_group 1;" ::: "memory");    \
          else         asm volatile("cp.async.wait_group 0;" ::: "memory");    \
          QUADBAR();                                                           \
          const float* wbuf = sWS + kg * 4096 + (j & 1) * 2048 + ks * 128;     \
          _Pragma("unroll") for (int it = 0; it < 2; it++) {                   \
              const int fo = c * 64 + it * 32;                                 \
              float4 h0v = *(const float4*)((HB) + fo);                        \
              float4 h1v = *(const float4*)((HB) + 4 * SH_ROW + fo);           \
              float4 h2v = *(const float4*)((HB) + 8 * SH_ROW + fo);           \
              float4 h3v = *(const float4*)((HB) + 12 * SH_ROW + fo);          \
              const float* wr = wbuf + it * 1024;                              \
              DO_KK(0, x) DO_KK(1, y) DO_KK(2, z) DO_KK(3, w)                  \
          }                                                                    \
          QUADBAR();                                                           \
          if (j + 2 <= 11) { STREAM_CHUNK(j + 2) COMMIT(); }                   \
      }                                                                        \
      _Pragma("unroll") for (int i = 0; i < 4; i++)                            \
          _Pragma("unroll") for (int j2 = 0; j2 < 4; j2++) {                   \
              u64 a = acc[i][j2];                                              \
              a = add2(a, __shfl_xor_sync(0xffffffffu, a, 1));                 \
              a = add2(a, __shfl_xor_sync(0xffffffffu, a, 2));                 \
              a = add2(a, __shfl_xor_sync(0xffffffffu, a, 4));                 \
              acc[i][j2] = a; }                                                \
      if (ks == 0)                                                             \
          _Pragma("unroll") for (int i = 0; i < 4; i++)                        \
              _Pragma("unroll") for (int j2 = 0; j2 < 4; j2++)                 \
                  (RED)[(kg * 16 + i * 4 + q) * 16 + ng4 * 4 + j2] = acc[i][j2]; }
#define SUM4(R) add2(add2((R)[(0 * 16 + warp) * 16 + lane], (R)[(1 * 16 + warp) * 16 + lane]), \
                     add2((R)[(2 * 16 + warp) * 16 + lane], (R)[(3 * 16 + warp) * 16 + lane]))

    for (int t = 1; t <= S_ + 1; t++) {
        // group A: sH0 <- h0(min(t-1,511)) + sPre <- pre0(min(t,511))
        {
            int tr = (t - 1 < S_) ? (t - 1) : (S_ - 1);
            const int* fl = &flags0[tr * 16 + bg * 4 + kg];
            while (ld_acq(fl) < 128) { }
            const float* src = buf0 + ((size_t)tr * B_ + b0) * H_ + kg * 256;
#pragma unroll
            for (int i = 0; i < 8; i++) {
                int v = gtid + i * 128, r = v >> 6, cc = v & 63;
                cpasync16(&sH0[r * SH_ROW + kg * 256 + cc * 4], src + (size_t)r * H_ + cc * 4);
            }
            if (gtid < 32) {
                int r = kg * 4 + (gtid >> 3), cc = (gtid & 7) * 4;
                int ts = (t < S_) ? t : (S_ - 1);
                cpasync16(&sPre[r * 32 + cc], buf0 + ((size_t)ts * B_ + b0 + r) * H_ + n0 + cc);
            }
        }
        COMMIT();
        // group B: sH1 <- h1(t-3) (t>=3; else harmless row 0)
        {
            int sr = (t >= 3) ? (t - 3) : 0;
            if (t >= 3) {
                const int* fl = &flags1[sr * 16 + bg * 4 + kg];
                while (ld_acq(fl) < 128) { }
            }
            const float* src = buf1 + ((size_t)sr * B_ + b0) * H_ + kg * 256;
#pragma unroll
            for (int i = 0; i < 8; i++) {
                int v = gtid + i * 128, r = v >> 6, cc = v & 63;
                cpasync16(&sH1[r * SH_ROW + kg * 256 + cc * 4], src + (size_t)r * H_ + cc * 4);
            }
        }
        COMMIT();
        STREAM_CHUNK(0) COMMIT();
        STREAM_CHUNK(1) COMMIT();

        MATVEC(0, h0b, redL0)          // L0: W0hh . h0(t-1)
        __syncthreads();
        if (t < S_) {
            if (lane < 16) {
                u64 s = SUM4(redL0);
                s = add2(s, *(const u64*)&sPre[warp * 32 + lane * 2]);
                float2 v = unpk(s);
                *(u64*)(buf0 + ((size_t)t * B_ + b0 + warp) * H_ + n0 + lane * 2)
                    = pack2(tanhf(v.x), tanhf(v.y));
            }
            __syncwarp();
            if (lane == 0) red_release(&flags0[t * 16 + bg * 4 + mychunk]);
        }

        MATVEC(1, h0b, redP1)          // pre1 for s=t-1: W1ih . h0(t-1)
        __syncthreads();
        if (lane < 16) pregNew = add2(SUM4(redP1), biasv);

        MATVEC(2, h1b, redL1)          // L1: W1hh . h1(t-3)
        __syncthreads();
        if (t == 2) {
            if (lane < 16) {
                float2 v = unpk(pregOld);
                *(u64*)(buf1 + ((size_t)(b0 + warp)) * H_ + n0 + lane * 2)
                    = pack2(tanhf(v.x), tanhf(v.y));
            }
            __syncwarp();
            if (lane == 0) red_release(&flags1[0 * 16 + bg * 4 + mychunk]);
        } else if (t >= 3) {
            if (lane < 16) {
                u64 s = add2(SUM4(redL1), pregOld);
                float2 v = unpk(s);
                *(u64*)(buf1 + ((size_t)(t - 2) * B_ + b0 + warp) * H_ + n0 + lane * 2)
                    = pack2(tanhf(v.x), tanhf(v.y));
            }
            __syncwarp();
            if (lane == 0) red_release(&flags1[(t - 2) * 16 + bg * 4 + mychunk]);
        }
        pregOld = pregNew;
    }
#undef SUM4
#undef MATVEC
#undef DO_KK
#undef STREAM_CHUNK
#undef COMMIT
#undef QUADBAR
}

// ---------------------------------------------------------------------------

extern "C" void kernel_launch(void* const* d_in, const int* in_sizes, int n_in,
                              void* d_out, int out_size) {
    const float* x      = (const float*)d_in[0];
    const float* W_ih_0 = (const float*)d_in[1];
    const float* W_hh_0 = (const float*)d_in[2];
    const float* b_ih_0 = (const float*)d_in[3];
    const float* b_hh_0 = (const float*)d_in[4];
    const float* W_ih_1 = (const float*)d_in[5];
    const float* W_hh_1 = (const float*)d_in[6];
    const float* b_ih_1 = (const float*)d_in[7];
    const float* b_hh_1 = (const float*)d_in[8];
    const float* fc_w   = (const float*)d_in[9];
    const float* fc_b   = (const float*)d_in[10];
    float* out = (float*)d_out;

    float *buf0, *buf1, *blob;
    int* flags;
    cudaGetSymbolAddress((void**)&buf0, g_buf0);
    cudaGetSymbolAddress((void**)&buf1, g_buf1);
    cudaGetSymbolAddress((void**)&blob, g_wblob);
    cudaGetSymbolAddress((void**)&flags, g_flags);

    // smem: 2*16448(h) + 16384(stream) + 3*2048(red) + 512(pre) floats
    const int fsmem = (2 * SHF + 16384 + 6144 + 512) * 4;   // 223744 B
    static bool attr_set = false;
    if (!attr_set) {
        cudaFuncSetAttribute(fused_k, cudaFuncAttributeMaxDynamicSharedMemorySize, fsmem);
        attr_set = true;
    }

    zero_flags_k<<<16, 1024>>>(flags);
    wprep_k<<<dim3(32, 32, 3), 256>>>(W_hh_0, W_ih_1, W_hh_1, blob);
    // pre0[s][b][h] = x @ W_ih_0^T + (b_ih_0 + b_hh_0)
    gemm_k<I_, 0, 0><<<dim3(H_ / 128, S_), 128>>>(x, W_ih_0, b_ih_0, b_hh_0, buf0);
    // fused L0 + pre1 + L1
    fused_k<<<128, 512, fsmem>>>(blob, b_ih_1, b_hh_1, buf0, buf1, flags);
    // out[b][s][o] = hs1 @ fc_w^T + fc_b
    gemm_k<H_, 1, 1><<<dim3(O_ / 128, S_), 128>>>(buf1, fc_w, fc_b, nullptr, out);
}

// round 11
// speedup vs baseline: 1.0027x; 1.0027x over previous
#include <cuda_runtime.h>
#include <math.h>

#define B_ 64
#define S_ 512
#define I_ 256
#define H_ 1024
#define O_ 256

__device__ float g_buf0[S_ * B_ * H_];
__device__ float g_buf1[S_ * B_ * H_];
// Pre-swizzled weight blob: [mat(3: W0hh,W1ih,W1hh)][ng(32)][k(1024)][32]
__device__ float g_wblob[3 * 32 * 1024 * 32];
// flags0 then flags1: [t(512)][bg(4)][chunk(4)], target 128 (8 CTAs x 16 warps)
__device__ int g_flags[2 * S_ * 16];

typedef unsigned long long u64;

__device__ __forceinline__ u64 pack2(float x, float y) {
    u64 r; asm("mov.b64 %0,{%1,%2};" : "=l"(r) : "f"(x), "f"(y)); return r;
}
__device__ __forceinline__ u64 fma2(u64 a, u64 b, u64 c) {
    u64 d; asm("fma.rn.f32x2 %0,%1,%2,%3;" : "=l"(d) : "l"(a), "l"(b), "l"(c)); return d;
}
__device__ __forceinline__ u64 add2(u64 a, u64 b) {
    u64 d; asm("add.rn.f32x2 %0,%1,%2;" : "=l"(d) : "l"(a), "l"(b)); return d;
}
__device__ __forceinline__ float2 unpk(u64 v) {
    float2 f; asm("mov.b64 {%0,%1},%2;" : "=f"(f.x), "=f"(f.y) : "l"(v)); return f;
}
__device__ __forceinline__ void cpasync16(float* sdst, const float* gsrc) {
    unsigned sa = (unsigned)__cvta_generic_to_shared(sdst);
    asm volatile("cp.async.cg.shared.global [%0], [%1], 16;" :: "r"(sa), "l"(gsrc));
}
__device__ __forceinline__ int ld_acq(const int* p) {
    int v; asm volatile("ld.acquire.gpu.global.b32 %0, [%1];" : "=r"(v) : "l"(p) : "memory");
    return v;
}
__device__ __forceinline__ void red_release(int* p) {
    asm volatile("red.release.gpu.global.add.s32 [%0], 1;" :: "l"(p) : "memory");
}

__global__ void zero_flags_k(int* f) { f[blockIdx.x * 1024 + threadIdx.x] = 0; }

// Transpose+swizzle weights into blob. block=(kt, ng, m), 256 thr.
__global__ void __launch_bounds__(256) wprep_k(const float* __restrict__ W0hh,
                                               const float* __restrict__ W1ih,
                                               const float* __restrict__ W1hh,
                                               float* __restrict__ blob) {
    __shared__ float s[32][33];
    const int kt = blockIdx.x, ng = blockIdx.y, m = blockIdx.z;
    const float* W = (m == 0) ? W0hh : (m == 1) ? W1ih : W1hh;
    const int tid = threadIdx.x;
#pragma unroll
    for (int it = 0; it < 4; it++) {
        int idx = tid + it * 256;
        int j = idx >> 5, kk = idx & 31;
        s[j][kk] = W[(size_t)(ng * 32 + j) * H_ + kt * 32 + kk];
    }
    __syncthreads();
#pragma unroll
    for (int it = 0; it < 4; it++) {
        int idx = tid + it * 256;
        int kk = idx >> 5, j = idx & 31;
        int k = kt * 32 + kk;
        int sw = (((j >> 2) ^ ((k >> 2) & 7)) << 2) | (j & 3);
        blob[((size_t)(m * 32 + ng) * 1024 + k) * 32 + sw] = s[j][kk];
    }
}

// ---------------------------------------------------------------------------
// Tiled fp32 GEMM (unchanged) — pre0 and fc only.
// ---------------------------------------------------------------------------
template <int K, int AROW, int CROW>
__global__ void __launch_bounds__(128) gemm_k(const float* __restrict__ A,
                                              const float* __restrict__ W,
                                              const float* __restrict__ b1,
                                              const float* __restrict__ b2,
                                              float* __restrict__ C) {
    __shared__ __align__(16) float sA[32][68];
    __shared__ __align__(16) float sB[32][132];
    const int s = blockIdx.y, n0 = blockIdx.x * 128, tid = threadIdx.x;
    const int tm = tid & 7, tn = tid >> 3;
    u64 acc[8][4];
#pragma unroll
    for (int i = 0; i < 8; i++)
#pragma unroll
        for (int j = 0; j < 4; j++) acc[i][j] = 0ull;
    for (int kc = 0; kc < K; kc += 32) {
#pragma unroll
        for (int i = 0; i < 4; i++) {
            int v = tid + i * 128, b = v >> 3, kq = v & 7;
            size_t row = AROW ? ((size_t)s * B_ + b) : ((size_t)b * S_ + s);
            float4 f = __ldg((const float4*)(A + row * K + kc + kq * 4));
            sA[kq * 4 + 0][b] = f.x; sA[kq * 4 + 1][b] = f.y;
            sA[kq * 4 + 2][b] = f.z; sA[kq * 4 + 3][b] = f.w;
        }
#pragma unroll
        for (int i = 0; i < 8; i++) {
            int v = tid + i * 128, n = v >> 3, kq = v & 7;
            float4 f = __ldg((const float4*)(W + (size_t)(n0 + n) * K + kc + kq * 4));
            sB[kq * 4 + 0][n] = f.x; sB[kq * 4 + 1][n] = f.y;
            sB[kq * 4 + 2][n] = f.z; sB[kq * 4 + 3][n] = f.w;
        }
        __syncthreads();
#pragma unroll
        for (int k = 0; k < 32; k++) {
            float4 a0 = *(const float4*)&sA[k][tm * 8];
            float4 a1 = *(const float4*)&sA[k][tm * 8 + 4];
            ulonglong2 w01 = *(const ulonglong2*)&sB[k][tn * 8];
            ulonglong2 w23 = *(const ulonglong2*)&sB[k][tn * 8 + 4];
            float av[8] = {a0.x, a0.y, a0.z, a0.w, a1.x, a1.y, a1.z, a1.w};
#pragma unroll
            for (int i = 0; i < 8; i++) {
                u64 ai = pack2(av[i], av[i]);
                acc[i][0] = fma2(ai, w01.x, acc[i][0]);
                acc[i][1] = fma2(ai, w01.y, acc[i][1]);
                acc[i][2] = fma2(ai, w23.x, acc[i][2]);
                acc[i][3] = fma2(ai, w23.y, acc[i][3]);
            }
        }
        __syncthreads();
    }
    float bias[8];
#pragma unroll
    for (int j8 = 0; j8 < 8; j8++) {
        int n = n0 + tn * 8 + j8;
        bias[j8] = b1[n] + (b2 ? b2[n] : 0.0f);
    }
    const int NC = CROW ? O_ : H_;
#pragma unroll
    for (int i = 0; i < 8; i++) {
        int b = tm * 8 + i;
        size_t row = CROW ? ((size_t)b * S_ + s) : ((size_t)s * B_ + b);
        float* Co = C + row * NC + n0 + tn * 8;
        float2 t0 = unpk(acc[i][0]), t1 = unpk(acc[i][1]);
        float2 t2 = unpk(acc[i][2]), t3 = unpk(acc[i][3]);
        *(float4*)Co       = make_float4(t0.x + bias[0], t0.y + bias[1],
                                         t1.x + bias[2], t1.y + bias[3]);
        *(float4*)(Co + 4) = make_float4(t2.x + bias[4], t2.y + bias[5],
                                         t3.x + bias[6], t3.y + bias[7]);
    }
}

// ---------------------------------------------------------------------------
// Fused 2-layer RNN. Iter t (1..513): L0 step t (t<512), pre1 matvec for
// t-1 (t<=512), L1 step t-2 (t>=2). Weights streamed from blob in 8KB
// double-buffered chunks per quad (12 chunks/iter: m0 c0..3, m1, m2).
// ---------------------------------------------------------------------------
#define SH_ROW 1028
#define SHF    (16 * SH_ROW)   // 16448 f per h stage

__global__ void __launch_bounds__(512) fused_k(const float* __restrict__ blob,
                                               const float* __restrict__ bi1,
                                               const float* __restrict__ bh1,
                                               float* __restrict__ buf0,
                                               float* __restrict__ buf1,
                                               int* __restrict__ flags) {
    extern __shared__ __align__(16) float smem[];
    float* sH0 = smem;                       // [16][1028]
    float* sH1 = smem + SHF;                 // [16][1028]
    float* sWS = smem + 2 * SHF;             // [4 quads][2][2048]
    u64* redL0 = (u64*)(sWS + 16384);        // 1024 u64 each
    u64* redP1 = redL0 + 1024;
    u64* redL1 = redP1 + 1024;
    float* sPre = (float*)(redL1 + 1024);    // [16][32]

    const int tid = threadIdx.x;
    const int warp = tid >> 5, lane = tid & 31;
    const int ng4 = warp & 3, kg = warp >> 2;
    const int ks = lane & 7, q = lane >> 3;
    const int bg = blockIdx.x & 3, ng = blockIdx.x >> 2;
    const int n0 = ng * 32, b0 = bg * 16;
    const int ca = (((ng4 * 2) ^ ks) << 2), cb = ca ^ 4;
    const int mychunk = ng >> 3;
    const int gtid = tid & 127;
    int* flags0 = flags;
    int* flags1 = flags + S_ * 16;

    u64 biasv = 0, pregOld = 0, pregNew = 0;
    if (lane < 16) {
        int n = n0 + lane * 2;
        biasv = pack2(bi1[n] + bh1[n], bi1[n + 1] + bh1[n + 1]);
    }

    // t=0: h0_0 = tanh(pre0_0)
    if (lane < 16) {
        float* a = buf0 + ((size_t)(b0 + warp)) * H_ + n0 + lane * 2;
        float2 v = unpk(*(const u64*)a);
        *(u64*)a = pack2(tanhf(v.x), tanhf(v.y));
    }
    __syncwarp();
    if (lane == 0) red_release(&flags0[0 * 16 + bg * 4 + mychunk]);
    __syncthreads();

    const float* h0b = sH0 + q * SH_ROW + kg * 256 + ks * 4;
    const float* h1b = sH1 + q * SH_ROW + kg * 256 + ks * 4;

#define QUADBAR() asm volatile("bar.sync %0, 128;" :: "r"(1 + kg) : "memory")
#define COMMIT()  asm volatile("cp.async.commit_group;")
#define STREAM_CHUNK(J)                                                        \
    { const float* src_ = blob + ((size_t)(((J) >> 2) * 32 + ng) * 1024        \
                                  + kg * 256 + ((J) & 3) * 64) * 32;           \
      float* dst_ = sWS + kg * 4096 + ((J) & 1) * 2048;                        \
      _Pragma("unroll") for (int i_ = 0; i_ < 4; i_++)                         \
          cpasync16(dst_ + (gtid + i_ * 128) * 4, src_ + (gtid + i_ * 128) * 4); }
#define DO_KK(KK, CMP)                                                         \
    { ulonglong2 wa = *(const ulonglong2*)(wr + KK * 32 + ca);                 \
      ulonglong2 wb = *(const ulonglong2*)(wr + KK * 32 + cb);                 \
      u64 p0 = pack2(h0v.CMP, h0v.CMP); u64 p1 = pack2(h1v.CMP, h1v.CMP);      \
      u64 p2 = pack2(h2v.CMP, h2v.CMP); u64 p3 = pack2(h3v.CMP, h3v.CMP);      \
      acc[0][0] = fma2(p0, wa.x, acc[0][0]); acc[0][1] = fma2(p0, wa.y, acc[0][1]); \
      acc[0][2] = fma2(p0, wb.x, acc[0][2]); acc[0][3] = fma2(p0, wb.y, acc[0][3]); \
      acc[1][0] = fma2(p1, wa.x, acc[1][0]); acc[1][1] = fma2(p1, wa.y, acc[1][1]); \
      acc[1][2] = fma2(p1, wb.x, acc[1][2]); acc[1][3] = fma2(p1, wb.y, acc[1][3]); \
      acc[2][0] = fma2(p2, wa.x, acc[2][0]); acc[2][1] = fma2(p2, wa.y, acc[2][1]); \
      acc[2][2] = fma2(p2, wb.x, acc[2][2]); acc[2][3] = fma2(p2, wb.y, acc[2][3]); \
      acc[3][0] = fma2(p3, wa.x, acc[3][0]); acc[3][1] = fma2(p3, wa.y, acc[3][1]); \
      acc[3][2] = fma2(p3, wb.x, acc[3][2]); acc[3][3] = fma2(p3, wb.y, acc[3][3]); }
#define MATVEC(MB, HB, RED)                                                    \
    { u64 acc[4][4];                                                           \
      _Pragma("unroll") for (int i = 0; i < 4; i++)                            \
          _Pragma("unroll") for (int j2 = 0; j2 < 4; j2++) acc[i][j2] = 0ull;  \
      _Pragma("unroll")                                                        \
      for (int c = 0; c < 4; c++) {                                            \
          const int j = (MB) * 4 + c;                                          \
          if (j <= 10) asm volatile("cp.async.wait_group 1;" ::: "memory");    \
          else         asm volatile("cp.async.wait_group 0;" ::: "memory");    \
          QUADBAR();                                                           \
          const float* wbuf = sWS + kg * 4096 + (j & 1) * 2048 + ks * 128;     \
          _Pragma("unroll") for (int it = 0; it < 2; it++) {                   \
              const int fo = c * 64 + it * 32;                                 \
              float4 h0v = *(const float4*)((HB) + fo);                        \
              float4 h1v = *(const float4*)((HB) + 4 * SH_ROW + fo);           \
              float4 h2v = *(const float4*)((HB) + 8 * SH_ROW + fo);           \
              float4 h3v = *(const float4*)((HB) + 12 * SH_ROW + fo);          \
              const float* wr = wbuf + it * 1024;                              \
              DO_KK(0, x) DO_KK(1, y) DO_KK(2, z) DO_KK(3, w)                  \
          }                                                                    \
          QUADBAR();                                                           \
          if (j + 2 <= 11) { STREAM_CHUNK(j + 2) COMMIT(); }                   \
      }                                                                        \
      _Pragma("unroll") for (int i = 0; i < 4; i++)                            \
          _Pragma("unroll") for (int j2 = 0; j2 < 4; j2++) {                   \
              u64 a = acc[i][j2];                                              \
              a = add2(a, __shfl_xor_sync(0xffffffffu, a, 1));                 \
              a = add2(a, __shfl_xor_sync(0xffffffffu, a, 2));                 \
              a = add2(a, __shfl_xor_sync(0xffffffffu, a, 4));                 \
              acc[i][j2] = a; }                                                \
      if (ks == 0)                                                             \
          _Pragma("unroll") for (int i = 0; i < 4; i++)                        \
              _Pragma("unroll") for (int j2 = 0; j2 < 4; j2++)                 \
                  (RED)[(kg * 16 + i * 4 + q) * 16 + ng4 * 4 + j2] = acc[i][j2]; }
#define SUM4(R) add2(add2((R)[(0 * 16 + warp) * 16 + lane], (R)[(1 * 16 + warp) * 16 + lane]), \
                     add2((R)[(2 * 16 + warp) * 16 + lane], (R)[(3 * 16 + warp) * 16 + lane]))

    for (int t = 1; t <= S_ + 1; t++) {
        // group A: sH0 <- h0(min(t-1,511)) + sPre <- pre0(min(t,511))
        {
            int tr = (t - 1 < S_) ? (t - 1) : (S_ - 1);
            const int* fl = &flags0[tr * 16 + bg * 4 + kg];
            while (ld_acq(fl) < 128) { }
            const float* src = buf0 + ((size_t)tr * B_ + b0) * H_ + kg * 256;
#pragma unroll
            for (int i = 0; i < 8; i++) {
                int v = gtid + i * 128, r = v >> 6, cc = v & 63;
                cpasync16(&sH0[r * SH_ROW + kg * 256 + cc * 4], src + (size_t)r * H_ + cc * 4);
            }
            if (gtid < 32) {
                int r = kg * 4 + (gtid >> 3), cc = (gtid & 7) * 4;
                int ts = (t < S_) ? t : (S_ - 1);
                cpasync16(&sPre[r * 32 + cc], buf0 + ((size_t)ts * B_ + b0 + r) * H_ + n0 + cc);
            }
        }
        COMMIT();
        // group B: sH1 <- h1(t-3) (t>=3; else harmless row 0)
        {
            int sr = (t >= 3) ? (t - 3) : 0;
            if (t >= 3) {
                const int* fl = &flags1[sr * 16 + bg * 4 + kg];
                while (ld_acq(fl) < 128) { }
            }
            const float* src = buf1 + ((size_t)sr * B_ + b0) * H_ + kg * 256;
#pragma unroll
            for (int i = 0; i < 8; i++) {
                int v = gtid + i * 128, r = v >> 6, cc = v & 63;
                cpasync16(&sH1[r * SH_ROW + kg * 256 + cc * 4], src + (size_t)r * H_ + cc * 4);
            }
        }
        COMMIT();
        STREAM_CHUNK(0) COMMIT();
        STREAM_CHUNK(1) COMMIT();

        MATVEC(0, h0b, redL0)          // L0: W0hh . h0(t-1)
        __syncthreads();
        if (t < S_) {
            if (lane < 16) {
                u64 s = SUM4(redL0);
                s = add2(s, *(const u64*)&sPre[warp * 32 + lane * 2]);
                float2 v = unpk(s);
                *(u64*)(buf0 + ((size_t)t * B_ + b0 + warp) * H_ + n0 + lane * 2)
                    = pack2(tanhf(v.x), tanhf(v.y));
            }
            __syncwarp();
            if (lane == 0) red_release(&flags0[t * 16 + bg * 4 + mychunk]);
        }

        MATVEC(1, h0b, redP1)          // pre1 for s=t-1: W1ih . h0(t-1)
        __syncthreads();
        if (lane < 16) pregNew = add2(SUM4(redP1), biasv);

        MATVEC(2, h1b, redL1)          // L1: W1hh . h1(t-3)
        __syncthreads();
        if (t == 2) {
            if (lane < 16) {
                float2 v = unpk(pregOld);
                *(u64*)(buf1 + ((size_t)(b0 + warp)) * H_ + n0 + lane * 2)
                    = pack2(tanhf(v.x), tanhf(v.y));
            }
            __syncwarp();
            if (lane == 0) red_release(&flags1[0 * 16 + bg * 4 + mychunk]);
        } else if (t >= 3) {
            if (lane < 16) {
                u64 s = add2(SUM4(redL1), pregOld);
                float2 v = unpk(s);
                *(u64*)(buf1 + ((size_t)(t - 2) * B_ + b0 + warp) * H_ + n0 + lane * 2)
                    = pack2(tanhf(v.x), tanhf(v.y));
            }
            __syncwarp();
            if (lane == 0) red_release(&flags1[(t - 2) * 16 + bg * 4 + mychunk]);
        }
        pregOld = pregNew;
    }
#undef SUM4
#undef MATVEC
#undef DO_KK
#undef STREAM_CHUNK
#undef COMMIT
#undef QUADBAR
}

// ---------------------------------------------------------------------------

extern "C" void kernel_launch(void* const* d_in, const int* in_sizes, int n_in,
                              void* d_out, int out_size) {
    const float* x      = (const float*)d_in[0];
    const float* W_ih_0 = (const float*)d_in[1];
    const float* W_hh_0 = (const float*)d_in[2];
    const float* b_ih_0 = (const float*)d_in[3];
    const float* b_hh_0 = (const float*)d_in[4];
    const float* W_ih_1 = (const float*)d_in[5];
    const float* W_hh_1 = (const float*)d_in[6];
    const float* b_ih_1 = (const float*)d_in[7];
    const float* b_hh_1 = (const float*)d_in[8];
    const float* fc_w   = (const float*)d_in[9];
    const float* fc_b   = (const float*)d_in[10];
    float* out = (float*)d_out;

    float *buf0, *buf1, *blob;
    int* flags;
    cudaGetSymbolAddress((void**)&buf0, g_buf0);
    cudaGetSymbolAddress((void**)&buf1, g_buf1);
    cudaGetSymbolAddress((void**)&blob, g_wblob);
    cudaGetSymbolAddress((void**)&flags, g_flags);

    // smem: 2*16448(h) + 16384(stream) + 3*2048(red) + 512(pre) floats
    const int fsmem = (2 * SHF + 16384 + 6144 + 512) * 4;   // 223744 B
    static bool attr_set = false;
    if (!attr_set) {
        cudaFuncSetAttribute(fused_k, cudaFuncAttributeMaxDynamicSharedMemorySize, fsmem);
        attr_set = true;
    }

    zero_flags_k<<<16, 1024>>>(flags);
    wprep_k<<<dim3(32, 32, 3), 256>>>(W_hh_0, W_ih_1, W_hh_1, blob);
    // pre0[s][b][h] = x @ W_ih_0^T + (b_ih_0 + b_hh_0)
    gemm_k<I_, 0, 0><<<dim3(H_ / 128, S_), 128>>>(x, W_ih_0, b_ih_0, b_hh_0, buf0);
    // fused L0 + pre1 + L1
    fused_k<<<128, 512, fsmem>>>(blob, b_ih_1, b_hh_1, buf0, buf1, flags);
    // out[b][s][o] = hs1 @ fc_w^T + fc_b
    gemm_k<H_, 1, 1><<<dim3(O_ / 128, S_), 128>>>(buf1, fc_w, fc_b, nullptr, out);
}

// round 13
// speedup vs baseline: 1.2545x; 1.2511x over previous
#include <cuda_runtime.h>
#include <cuda_bf16.h>
#include <math.h>

#define B_ 64
#define S_ 512
#define I_ 256
#define H_ 1024
#define O_ 256

__device__ float g_buf0[S_ * B_ * H_];
__device__ float g_buf1[S_ * B_ * H_];
__device__ int g_flags[2 * S_ * 16];
__device__ __nv_bfloat16 g_ahi[S_ * B_ * H_];
__device__ __nv_bfloat16 g_alo[S_ * B_ * H_];
__device__ __nv_bfloat16 g_bhi[H_ * H_];
__device__ __nv_bfloat16 g_blo[H_ * H_];

typedef unsigned long long u64;
typedef unsigned int u32;

__device__ __forceinline__ u64 pack2(float x, float y) {
    u64 r; asm("mov.b64 %0,{%1,%2};" : "=l"(r) : "f"(x), "f"(y)); return r;
}
__device__ __forceinline__ u64 fma2(u64 a, u64 b, u64 c) {
    u64 d; asm("fma.rn.f32x2 %0,%1,%2,%3;" : "=l"(d) : "l"(a), "l"(b), "l"(c)); return d;
}
__device__ __forceinline__ u64 add2(u64 a, u64 b) {
    u64 d; asm("add.rn.f32x2 %0,%1,%2;" : "=l"(d) : "l"(a), "l"(b)); return d;
}
__device__ __forceinline__ float2 unpk(u64 v) {
    float2 f; asm("mov.b64 {%0,%1},%2;" : "=f"(f.x), "=f"(f.y) : "l"(v)); return f;
}
__device__ __forceinline__ void cpasync16(void* sdst, const void* gsrc) {
    unsigned sa = (unsigned)__cvta_generic_to_shared(sdst);
    asm volatile("cp.async.cg.shared.global [%0], [%1], 16;" :: "r"(sa), "l"(gsrc));
}
__device__ __forceinline__ void cpasync16r(unsigned sdst, const void* gsrc) {
    asm volatile("cp.async.cg.shared.global [%0], [%1], 16;" :: "r"(sdst), "l"(gsrc));
}
__device__ __forceinline__ int ld_acq(const int* p) {
    int v; asm volatile("ld.acquire.gpu.global.b32 %0, [%1];" : "=r"(v) : "l"(p) : "memory");
    return v;
}
__device__ __forceinline__ void red_release(int* p) {
    asm volatile("red.release.gpu.global.add.s32 [%0], 1;" :: "l"(p) : "memory");
}
__device__ __forceinline__ unsigned smem_u32(const void* p) {
    unsigned a; asm("{ .reg .u64 t; cvta.to.shared.u64 t, %1; cvt.u32.u64 %0, t; }" : "=r"(a) : "l"(p));
    return a;
}

__global__ void zero_flags_k(int* f) { f[blockIdx.x * 1024 + threadIdx.x] = 0; }

__global__ void __launch_bounds__(256) split_k(const float* __restrict__ src,
                                               __nv_bfloat16* __restrict__ hi,
                                               __nv_bfloat16* __restrict__ lo) {
    int i = blockIdx.x * 256 + threadIdx.x;
    float4 v = __ldg((const float4*)src + i);
    float f[4] = {v.x, v.y, v.z, v.w};
    __nv_bfloat16 h[4], l[4];
#pragma unroll
    for (int j = 0; j < 4; j++) {
        h[j] = __float2bfloat16(f[j]);
        l[j] = __float2bfloat16(f[j] - __bfloat162float(h[j]));
    }
    ((uint2*)hi)[i] = *(uint2*)h;
    ((uint2*)lo)[i] = *(uint2*)l;
}

// fp32 GEMM (R6) — pre0 only.
template <int K, int AROW, int CROW>
__global__ void __launch_bounds__(128) gemm_k(const float* __restrict__ A,
                                              const float* __restrict__ W,
                                              const float* __restrict__ b1,
                                              const float* __restrict__ b2,
                                              float* __restrict__ C) {
    __shared__ __align__(16) float sA[32][68];
    __shared__ __align__(16) float sB[32][132];
    const int s = blockIdx.y, n0 = blockIdx.x * 128, tid = threadIdx.x;
    const int tm = tid & 7, tn = tid >> 3;
    u64 acc[8][4];
#pragma unroll
    for (int i = 0; i < 8; i++)
#pragma unroll
        for (int j = 0; j < 4; j++) acc[i][j] = 0ull;
    for (int kc = 0; kc < K; kc += 32) {
#pragma unroll
        for (int i = 0; i < 4; i++) {
            int v = tid + i * 128, b = v >> 3, kq = v & 7;
            size_t row = AROW ? ((size_t)s * B_ + b) : ((size_t)b * S_ + s);
            float4 f = __ldg((const float4*)(A + row * K + kc + kq * 4));
            sA[kq * 4 + 0][b] = f.x; sA[kq * 4 + 1][b] = f.y;
            sA[kq * 4 + 2][b] = f.z; sA[kq * 4 + 3][b] = f.w;
        }
#pragma unroll
        for (int i = 0; i < 8; i++) {
            int v = tid + i * 128, n = v >> 3, kq = v & 7;
            float4 f = __ldg((const float4*)(W + (size_t)(n0 + n) * K + kc + kq * 4));
            sB[kq * 4 + 0][n] = f.x; sB[kq * 4 + 1][n] = f.y;
            sB[kq * 4 + 2][n] = f.z; sB[kq * 4 + 3][n] = f.w;
        }
        __syncthreads();
#pragma unroll
        for (int k = 0; k < 32; k++) {
            float4 a0 = *(const float4*)&sA[k][tm * 8];
            float4 a1 = *(const float4*)&sA[k][tm * 8 + 4];
            ulonglong2 w01 = *(const ulonglong2*)&sB[k][tn * 8];
            ulonglong2 w23 = *(const ulonglong2*)&sB[k][tn * 8 + 4];
            float av[8] = {a0.x, a0.y, a0.z, a0.w, a1.x, a1.y, a1.z, a1.w};
#pragma unroll
            for (int i = 0; i < 8; i++) {
                u64 ai = pack2(av[i], av[i]);
                acc[i][0] = fma2(ai, w01.x, acc[i][0]);
                acc[i][1] = fma2(ai, w01.y, acc[i][1]);
                acc[i][2] = fma2(ai, w23.x, acc[i][2]);
                acc[i][3] = fma2(ai, w23.y, acc[i][3]);
            }
        }
        __syncthreads();
    }
    float bias[8];
#pragma unroll
    for (int j8 = 0; j8 < 8; j8++) {
        int n = n0 + tn * 8 + j8;
        bias[j8] = b1[n] + (b2 ? b2[n] : 0.0f);
    }
    const int NC = CROW ? O_ : H_;
#pragma unroll
    for (int i = 0; i < 8; i++) {
        int b = tm * 8 + i;
        size_t row = CROW ? ((size_t)b * S_ + s) : ((size_t)s * B_ + b);
        float* Co = C + row * NC + n0 + tn * 8;
        float2 t0 = unpk(acc[i][0]), t1 = unpk(acc[i][1]);
        float2 t2 = unpk(acc[i][2]), t3 = unpk(acc[i][3]);
        *(float4*)Co       = make_float4(t0.x + bias[0], t0.y + bias[1], t1.x + bias[2], t1.y + bias[3]);
        *(float4*)(Co + 4) = make_float4(t2.x + bias[4], t2.y + bias[5], t3.x + bias[6], t3.y + bias[7]);
    }
}

// ---------------------------------------------------------------------------
// Split-bf16 mma.sync GEMM: C[m][n] = sum_k A[m][k] W[n][k] (+biases).
// 128(M)x64(N) CTA tile, 256 thr = 8 warps (4m x 2n), warp tile 32x32.
// K chunks of 32, double-buffered cp.async. smem rows: 40 halves (80B).
// CROW=0: C row = m, width H_.  CROW=1: C row = (m&63)*S_+(m>>6), width O_.
// ---------------------------------------------------------------------------
#define LDSM4(R, ADDR) asm volatile( \
    "ldmatrix.sync.aligned.m8n8.x4.shared.b16 {%0,%1,%2,%3}, [%4];" \
    : "=r"((R)[0]), "=r"((R)[1]), "=r"((R)[2]), "=r"((R)[3]) : "r"(ADDR))
#define LDSM2(R, ADDR) asm volatile( \
    "ldmatrix.sync.aligned.m8n8.x2.shared.b16 {%0,%1}, [%2];" \
    : "=r"((R)[0]), "=r"((R)[1]) : "r"(ADDR))
#define MMA16816(D, A, Bv) asm volatile( \
    "mma.sync.aligned.m16n8k16.row.col.f32.bf16.bf16.f32 " \
    "{%0,%1,%2,%3}, {%4,%5,%6,%7}, {%8,%9}, {%0,%1,%2,%3};" \
    : "+f"((D)[0]), "+f"((D)[1]), "+f"((D)[2]), "+f"((D)[3]) \
    : "r"((A)[0]), "r"((A)[1]), "r"((A)[2]), "r"((A)[3]), "r"((Bv)[0]), "r"((Bv)[1]))

template <int CROW, int HASB2>
__global__ void __launch_bounds__(256) mgemm_k(const __nv_bfloat16* __restrict__ Ahi,
                                               const __nv_bfloat16* __restrict__ Alo,
                                               const __nv_bfloat16* __restrict__ Bhi,
                                               const __nv_bfloat16* __restrict__ Blo,
                                               const float* __restrict__ b1,
                                               const float* __restrict__ b2,
                                               float* __restrict__ C) {
    extern __shared__ __nv_bfloat16 sm[];
    // halves offsets: A hi [2][5120], A lo @10240, W hi @20480 [2][2560], W lo @25600
    const unsigned smb = smem_u32(sm);
    const int tid = threadIdx.x, lane = tid & 31, warp = tid >> 5;
    const int wm = warp >> 1, wn = warp & 1;
    const int m0 = blockIdx.y * 128, n0g = blockIdx.x * 64;

    float acc[2][4][4];
#pragma unroll
    for (int i = 0; i < 2; i++)
#pragma unroll
        for (int j = 0; j < 4; j++)
#pragma unroll
            for (int e = 0; e < 4; e++) acc[i][j][e] = 0.0f;

#define ISSUE(CC)                                                              \
    { int kc_ = (CC) * 32; unsigned bs_ = (CC) & 1;                            \
      _Pragma("unroll") for (int i_ = 0; i_ < 2; i_++) {                       \
          int v_ = tid + i_ * 256, r_ = v_ >> 2, c4_ = v_ & 3;                 \
          cpasync16r(smb + (bs_ * 5120 + r_ * 40 + c4_ * 8) * 2,               \
                     Ahi + (size_t)(m0 + r_) * H_ + kc_ + c4_ * 8);            \
          cpasync16r(smb + (10240 + bs_ * 5120 + r_ * 40 + c4_ * 8) * 2,       \
                     Alo + (size_t)(m0 + r_) * H_ + kc_ + c4_ * 8);            \
      }                                                                        \
      { int r_ = tid >> 2, c4_ = tid & 3;                                      \
        cpasync16r(smb + (20480 + bs_ * 2560 + r_ * 40 + c4_ * 8) * 2,         \
                   Bhi + (size_t)(n0g + r_) * H_ + kc_ + c4_ * 8);             \
        cpasync16r(smb + (25600 + bs_ * 2560 + r_ * 40 + c4_ * 8) * 2,         \
                   Blo + (size_t)(n0g + r_) * H_ + kc_ + c4_ * 8);             \
      }                                                                        \
      asm volatile("cp.async.commit_group;"); }

    ISSUE(0)
    ISSUE(1)
    const int NCH = H_ / 32;
    for (int c = 0; c < NCH; c++) {
        if (c < NCH - 1) asm volatile("cp.async.wait_group 1;" ::: "memory");
        else             asm volatile("cp.async.wait_group 0;" ::: "memory");
        __syncthreads();
        const unsigned bs = c & 1;
        const unsigned ah = smb + (bs * 5120) * 2;
        const unsigned al = smb + (10240 + bs * 5120) * 2;
        const unsigned wh = smb + (20480 + bs * 2560) * 2;
        const unsigned wl = smb + (25600 + bs * 2560) * 2;
        const int arow = wm * 32 + (lane & 7) + ((lane & 8) ? 8 : 0);
        const int acolx = (lane & 16) ? 8 : 0;
        const int brow = wn * 32 + (lane & 7);
        const int bcolx = (lane & 8) ? 8 : 0;
#pragma unroll
        for (int ks = 0; ks < 2; ks++) {
            u32 a_h[2][4], a_l[2][4], b_h[4][2], b_l[4][2];
#pragma unroll
            for (int mi = 0; mi < 2; mi++) {
                unsigned off = ((arow + mi * 16) * 40 + ks * 16 + acolx) * 2;
                LDSM4(a_h[mi], ah + off);
                LDSM4(a_l[mi], al + off);
            }
#pragma unroll
            for (int ni = 0; ni < 4; ni++) {
                unsigned off = ((brow + ni * 8) * 40 + ks * 16 + bcolx) * 2;
                LDSM2(b_h[ni], wh + off);
                LDSM2(b_l[ni], wl + off);
            }
#pragma unroll
            for (int mi = 0; mi < 2; mi++)
#pragma unroll
                for (int ni = 0; ni < 4; ni++) {
                    MMA16816(acc[mi][ni], a_h[mi], b_h[ni]);
                    MMA16816(acc[mi][ni], a_h[mi], b_l[ni]);
                    MMA16816(acc[mi][ni], a_l[mi], b_h[ni]);
                }
        }
        __syncthreads();
        if (c + 2 < NCH) ISSUE(c + 2)
    }
#undef ISSUE

    const int NCW = CROW ? O_ : H_;
#pragma unroll
    for (int mi = 0; mi < 2; mi++) {
        int m = m0 + wm * 32 + mi * 16 + (lane >> 2);
        size_t r0 = CROW ? ((size_t)(m & 63) * S_ + (m >> 6)) : (size_t)m;
        size_t r1 = CROW ? ((size_t)((m + 8) & 63) * S_ + ((m + 8) >> 6)) : (size_t)(m + 8);
#pragma unroll
        for (int ni = 0; ni < 4; ni++) {
            int n = n0g + wn * 32 + ni * 8 + (lane & 3) * 2;
            float bv0 = __ldg(b1 + n) + (HASB2 ? __ldg(b2 + n) : 0.0f);
            float bv1 = __ldg(b1 + n + 1) + (HASB2 ? __ldg(b2 + n + 1) : 0.0f);
            *(float2*)(C + r0 * NCW + n) = make_float2(acc[mi][ni][0] + bv0, acc[mi][ni][1] + bv1);
            *(float2*)(C + r1 * NCW + n) = make_float2(acc[mi][ni][2] + bv0, acc[mi][ni][3] + bv1);
        }
    }
}

// Recurrence — R6 champion.
#define SW_F  (H_ * 32)
#define SH_ROW 1028
#define SH_F  (16 * SH_ROW)
#define RED_U64 1024

__global__ void __launch_bounds__(512) rnn_layer_kernel(const float* __restrict__ Whh,
                                                        float* __restrict__ buf,
                                                        int* __restrict__ flags) {
    extern __shared__ __align__(16) float smem[];
    float* sW = smem;
    float* sH = smem + SW_F;
    u64* red = (u64*)(sH + SH_F);
    float* sPre = (float*)(red + 2 * RED_U64);

    const int tid = threadIdx.x;
    const int warp = tid >> 5, lane = tid & 31;
    const int ng4 = warp & 3, kg = warp >> 2;
    const int ks = lane & 7, q = lane >> 3;
    const int bg = blockIdx.x & 3;
    const int n0 = (blockIdx.x >> 2) * 32;
    const int b0 = bg * 16;
    const int ca = (((ng4 * 2) ^ ks) << 2), cb = ca ^ 4;
    const int mychunk = n0 >> 8;
    const int gtid = tid & 127;

#pragma unroll
    for (int i = 0; i < 16; i++) {
        int v = tid + i * 512;
        int j = v >> 8, k4 = v & 255;
        float4 f = __ldg((const float4*)(Whh + (size_t)(n0 + j) * H_ + k4 * 4));
        int sw = (((j >> 2) ^ (k4 & 7)) << 2) + (j & 3);
        sW[(k4 * 4 + 0) * 32 + sw] = f.x;
        sW[(k4 * 4 + 1) * 32 + sw] = f.y;
        sW[(k4 * 4 + 2) * 32 + sw] = f.z;
        sW[(k4 * 4 + 3) * 32 + sw] = f.w;
    }

    if (lane < 16) {
        float* addr = buf + ((size_t)(b0 + warp)) * H_ + n0 + lane * 2;
        float2 v = unpk(*(const u64*)addr);
        *(u64*)addr = pack2(tanhf(v.x), tanhf(v.y));
    }
    __syncwarp();
    if (lane == 0) red_release(&flags[0 * 16 + bg * 4 + mychunk]);
    __syncthreads();

    const float* hb0 = sH + (0 * 4 + q) * SH_ROW + kg * 256 + ks * 4;
    const float* hb1 = sH + (1 * 4 + q) * SH_ROW + kg * 256 + ks * 4;
    const float* hb2 = sH + (2 * 4 + q) * SH_ROW + kg * 256 + ks * 4;
    const float* hb3 = sH + (3 * 4 + q) * SH_ROW + kg * 256 + ks * 4;
    const float* wbase = sW + (size_t)(kg * 256 + ks * 4) * 32;

    for (int t = 1; t < S_; t++) {
        u64* redw = red + (t & 1) * RED_U64;
        float* sPw = sPre + (t & 1) * 512;

        if (gtid < 32) {
            int r = kg * 4 + (gtid >> 3), c = (gtid & 7) * 4;
            cpasync16(&sPw[r * 32 + c], buf + ((size_t)t * B_ + b0 + r) * H_ + n0 + c);
        }
        if (gtid == 0) {
            const int* fl = &flags[(t - 1) * 16 + bg * 4 + kg];
            while (ld_acq(fl) < 128) { }
        }
        asm volatile("bar.sync %0, 128;" :: "r"(1 + kg) : "memory");
        {
            const float* src = buf + ((size_t)(t - 1) * B_ + b0) * H_ + kg * 256;
#pragma unroll
            for (int i = 0; i < 8; i++) {
                int v = gtid + i * 128;
                int r = v >> 6, c = v & 63;
                cpasync16(&sH[r * SH_ROW + kg * 256 + c * 4], src + (size_t)r * H_ + c * 4);
            }
            asm volatile("cp.async.wait_all;" ::: "memory");
            asm volatile("bar.sync %0, 128;" :: "r"(1 + kg) : "memory");
        }

        u64 acc[4][4];
#pragma unroll
        for (int i = 0; i < 4; i++)
#pragma unroll
            for (int j = 0; j < 4; j++) acc[i][j] = 0ull;

#pragma unroll
        for (int it = 0; it < 8; it++) {
            const int fo = it * 32;
            float4 h0 = *(const float4*)(hb0 + fo);
            float4 h1 = *(const float4*)(hb1 + fo);
            float4 h2 = *(const float4*)(hb2 + fo);
            float4 h3 = *(const float4*)(hb3 + fo);
            const float* wr = wbase + (size_t)fo * 32;
#define DO_KK(KK, CMP)                                                      \
            {                                                               \
                ulonglong2 wa = *(const ulonglong2*)(wr + KK * 32 + ca);    \
                ulonglong2 wb = *(const ulonglong2*)(wr + KK * 32 + cb);    \
                u64 p0 = pack2(h0.CMP, h0.CMP);                             \
                u64 p1 = pack2(h1.CMP, h1.CMP);                             \
                u64 p2 = pack2(h2.CMP, h2.CMP);                             \
                u64 p3 = pack2(h3.CMP, h3.CMP);                             \
                acc[0][0] = fma2(p0, wa.x, acc[0][0]);                      \
                acc[0][1] = fma2(p0, wa.y, acc[0][1]);                      \
                acc[0][2] = fma2(p0, wb.x, acc[0][2]);                      \
                acc[0][3] = fma2(p0, wb.y, acc[0][3]);                      \
                acc[1][0] = fma2(p1, wa.x, acc[1][0]);                      \
                acc[1][1] = fma2(p1, wa.y, acc[1][1]);                      \
                acc[1][2] = fma2(p1, wb.x, acc[1][2]);                      \
                acc[1][3] = fma2(p1, wb.y, acc[1][3]);                      \
                acc[2][0] = fma2(p2, wa.x, acc[2][0]);                      \
                acc[2][1] = fma2(p2, wa.y, acc[2][1]);                      \
                acc[2][2] = fma2(p2, wb.x, acc[2][2]);                      \
                acc[2][3] = fma2(p2, wb.y, acc[2][3]);                      \
                acc[3][0] = fma2(p3, wa.x, acc[3][0]);                      \
                acc[3][1] = fma2(p3, wa.y, acc[3][1]);                      \
                acc[3][2] = fma2(p3, wb.x, acc[3][2]);                      \
                acc[3][3] = fma2(p3, wb.y, acc[3][3]);                      \
            }
            DO_KK(0, x)
            DO_KK(1, y)
            DO_KK(2, z)
            DO_KK(3, w)
#undef DO_KK
        }

#pragma unroll
        for (int i = 0; i < 4; i++)
#pragma unroll
            for (int j = 0; j < 4; j++) {
                acc[i][j] = add2(acc[i][j], __shfl_xor_sync(0xffffffffu, acc[i][j], 1));
                acc[i][j] = add2(acc[i][j], __shfl_xor_sync(0xffffffffu, acc[i][j], 2));
                acc[i][j] = add2(acc[i][j], __shfl_xor_sync(0xffffffffu, acc[i][j], 4));
            }

        if (ks == 0) {
#pragma unroll
            for (int i = 0; i < 4; i++)
#pragma unroll
                for (int j = 0; j < 4; j++)
                    redw[(kg * 16 + (i * 4 + q)) * 16 + ng4 * 4 + j] = acc[i][j];
        }
        __syncthreads();

        if (lane < 16) {
            int b = warp, P = lane;
            u64 s01 = add2(redw[(0 * 16 + b) * 16 + P], redw[(1 * 16 + b) * 16 + P]);
            u64 s23 = add2(redw[(2 * 16 + b) * 16 + P], redw[(3 * 16 + b) * 16 + P]);
            u64 s = add2(s01, s23);
            s = add2(s, *(const u64*)&sPw[b * 32 + P * 2]);
            float2 v = unpk(s);
            *(u64*)(buf + ((size_t)t * B_ + b0 + b) * H_ + n0 + P * 2)
                = pack2(tanhf(v.x), tanhf(v.y));
        }
        __syncwarp();
        if (lane == 0) red_release(&flags[t * 16 + bg * 4 + mychunk]);
    }
}

extern "C" void kernel_launch(void* const* d_in, const int* in_sizes, int n_in,
                              void* d_out, int out_size) {
    const float* x      = (const float*)d_in[0];
    const float* W_ih_0 = (const float*)d_in[1];
    const float* W_hh_0 = (const float*)d_in[2];
    const float* b_ih_0 = (const float*)d_in[3];
    const float* b_hh_0 = (const float*)d_in[4];
    const float* W_ih_1 = (const float*)d_in[5];
    const float* W_hh_1 = (const float*)d_in[6];
    const float* b_ih_1 = (const float*)d_in[7];
    const float* b_hh_1 = (const float*)d_in[8];
    const float* fc_w   = (const float*)d_in[9];
    const float* fc_b   = (const float*)d_in[10];
    float* out = (float*)d_out;

    float *buf0, *buf1;
    int* flags;
    __nv_bfloat16 *ahi, *alo, *bhi, *blo;
    cudaGetSymbolAddress((void**)&buf0, g_buf0);
    cudaGetSymbolAddress((void**)&buf1, g_buf1);
    cudaGetSymbolAddress((void**)&flags, g_flags);
    cudaGetSymbolAddress((void**)&ahi, g_ahi);
    cudaGetSymbolAddress((void**)&alo, g_alo);
    cudaGetSymbolAddress((void**)&bhi, g_bhi);
    cudaGetSymbolAddress((void**)&blo, g_blo);

    const int rnn_smem = (SW_F + SH_F) * 4 + 2 * RED_U64 * 8 + 2 * 512 * 4;
    const int mg_smem  = 30720 * 2;   // 61440 B
    static bool attr_set = false;
    if (!attr_set) {
        cudaFuncSetAttribute(rnn_layer_kernel, cudaFuncAttributeMaxDynamicSharedMemorySize, rnn_smem);
        cudaFuncSetAttribute(mgemm_k<0, 1>, cudaFuncAttributeMaxDynamicSharedMemorySize, mg_smem);
        cudaFuncSetAttribute(mgemm_k<1, 0>, cudaFuncAttributeMaxDynamicSharedMemorySize, mg_smem);
        attr_set = true;
    }

    zero_flags_k<<<16, 1024>>>(flags);
    // pre0
    gemm_k<I_, 0, 0><<<dim3(H_ / 128, S_), 128>>>(x, W_ih_0, b_ih_0, b_hh_0, buf0);
    // L0 recurrence
    rnn_layer_kernel<<<128, 512, rnn_smem>>>(W_hh_0, buf0, flags);
    // split h0 and W1_ih, then pre1 via mma.sync
    split_k<<<(S_ * B_ * H_ / 4) / 256, 256>>>(buf0, ahi, alo);
    split_k<<<(H_ * H_ / 4) / 256, 256>>>(W_ih_1, bhi, blo);
    mgemm_k<0, 1><<<dim3(H_ / 64, (S_ * B_) / 128), 256, mg_smem>>>(
        ahi, alo, bhi, blo, b_ih_1, b_hh_1, buf1);
    // L1 recurrence
    rnn_layer_kernel<<<128, 512, rnn_smem>>>(W_hh_1, buf1, flags + S_ * 16);
    // split h1 and fc_w, then fc via mma.sync
    split_k<<<(S_ * B_ * H_ / 4) / 256, 256>>>(buf1, ahi, alo);
    split_k<<<(O_ * H_ / 4) / 256, 256>>>(fc_w, bhi, blo);
    mgemm_k<1, 0><<<dim3(O_ / 64, (S_ * B_) / 128), 256, mg_smem>>>(
        ahi, alo, bhi, blo, fc_b, nullptr, out);
}

// round 14
// speedup vs baseline: 1.2786x; 1.0192x over previous
#include <cuda_runtime.h>
#include <cuda_bf16.h>
#include <math.h>

#define B_ 64
#define S_ 512
#define I_ 256
#define H_ 1024
#define O_ 256

__device__ float g_buf0[S_ * B_ * H_];
__device__ float g_buf1[S_ * B_ * H_];
__device__ int g_flags[2 * S_ * 16];
__device__ __nv_bfloat16 g_ahi[S_ * B_ * H_];
__device__ __nv_bfloat16 g_alo[S_ * B_ * H_];
__device__ __nv_bfloat16 g_bhi[H_ * H_];
__device__ __nv_bfloat16 g_blo[H_ * H_];

typedef unsigned long long u64;
typedef unsigned int u32;

__device__ __forceinline__ u64 pack2(float x, float y) {
    u64 r; asm("mov.b64 %0,{%1,%2};" : "=l"(r) : "f"(x), "f"(y)); return r;
}
__device__ __forceinline__ u64 fma2(u64 a, u64 b, u64 c) {
    u64 d; asm("fma.rn.f32x2 %0,%1,%2,%3;" : "=l"(d) : "l"(a), "l"(b), "l"(c)); return d;
}
__device__ __forceinline__ u64 add2(u64 a, u64 b) {
    u64 d; asm("add.rn.f32x2 %0,%1,%2;" : "=l"(d) : "l"(a), "l"(b)); return d;
}
__device__ __forceinline__ float2 unpk(u64 v) {
    float2 f; asm("mov.b64 {%0,%1},%2;" : "=f"(f.x), "=f"(f.y) : "l"(v)); return f;
}
__device__ __forceinline__ void cpasync16(void* sdst, const void* gsrc) {
    unsigned sa = (unsigned)__cvta_generic_to_shared(sdst);
    asm volatile("cp.async.cg.shared.global [%0], [%1], 16;" :: "r"(sa), "l"(gsrc));
}
__device__ __forceinline__ void cpasync16r(unsigned sdst, const void* gsrc) {
    asm volatile("cp.async.cg.shared.global [%0], [%1], 16;" :: "r"(sdst), "l"(gsrc));
}
__device__ __forceinline__ int ld_acq(const int* p) {
    int v; asm volatile("ld.acquire.gpu.global.b32 %0, [%1];" : "=r"(v) : "l"(p) : "memory");
    return v;
}
__device__ __forceinline__ void red_release(int* p) {
    asm volatile("red.release.gpu.global.add.s32 [%0], 1;" :: "l"(p) : "memory");
}
__device__ __forceinline__ unsigned smem_u32(const void* p) {
    unsigned a; asm("{ .reg .u64 t; cvta.to.shared.u64 t, %1; cvt.u32.u64 %0, t; }" : "=r"(a) : "l"(p));
    return a;
}

__global__ void zero_flags_k(int* f) { f[blockIdx.x * 1024 + threadIdx.x] = 0; }

__global__ void __launch_bounds__(256) split_k(const float* __restrict__ src,
                                               __nv_bfloat16* __restrict__ hi,
                                               __nv_bfloat16* __restrict__ lo) {
    int i = blockIdx.x * 256 + threadIdx.x;
    float4 v = __ldg((const float4*)src + i);
    float f[4] = {v.x, v.y, v.z, v.w};
    __nv_bfloat16 h[4], l[4];
#pragma unroll
    for (int j = 0; j < 4; j++) {
        h[j] = __float2bfloat16(f[j]);
        l[j] = __float2bfloat16(f[j] - __bfloat162float(h[j]));
    }
    ((uint2*)hi)[i] = *(uint2*)h;
    ((uint2*)lo)[i] = *(uint2*)l;
}

// ---------------------------------------------------------------------------
// Split-bf16 mma.sync GEMM: C[m][n] = sum_k A[m][k] W[n][k] (+biases).
// 128(M)x64(N) CTA tile, 256 thr = 8 warps (4m x 2n), warp tile 32x32.
// K chunks of 32, 3-stage cp.async pipeline. smem rows: 40 halves (80B).
// CROW=0: row=m, width H_.       (pre1: m = s*64+b, buf layout)
// CROW=1: row=(m&63)*S_+(m>>6), width O_.   (fc out: [b][s][o])
// CROW=2: row=(m%S_)*64+(m/S_), width H_.   (pre0: m = b*S+s -> buf [s][b][h])
// ---------------------------------------------------------------------------
#define LDSM4(R, ADDR) asm volatile( \
    "ldmatrix.sync.aligned.m8n8.x4.shared.b16 {%0,%1,%2,%3}, [%4];" \
    : "=r"((R)[0]), "=r"((R)[1]), "=r"((R)[2]), "=r"((R)[3]) : "r"(ADDR))
#define LDSM2(R, ADDR) asm volatile( \
    "ldmatrix.sync.aligned.m8n8.x2.shared.b16 {%0,%1}, [%2];" \
    : "=r"((R)[0]), "=r"((R)[1]) : "r"(ADDR))
#define MMA16816(D, A, Bv) asm volatile( \
    "mma.sync.aligned.m16n8k16.row.col.f32.bf16.bf16.f32 " \
    "{%0,%1,%2,%3}, {%4,%5,%6,%7}, {%8,%9}, {%0,%1,%2,%3};" \
    : "+f"((D)[0]), "+f"((D)[1]), "+f"((D)[2]), "+f"((D)[3]) \
    : "r"((A)[0]), "r"((A)[1]), "r"((A)[2]), "r"((A)[3]), "r"((Bv)[0]), "r"((Bv)[1]))

#define STG_H 15360   // halves per stage: Ahi 5120 | Alo 5120 | Bhi 2560 | Blo 2560

template <int K, int CROW, int HASB2>
__global__ void __launch_bounds__(256) mgemm_k(const __nv_bfloat16* __restrict__ Ahi,
                                               const __nv_bfloat16* __restrict__ Alo,
                                               const __nv_bfloat16* __restrict__ Bhi,
                                               const __nv_bfloat16* __restrict__ Blo,
                                               const float* __restrict__ b1,
                                               const float* __restrict__ b2,
                                               float* __restrict__ C) {
    extern __shared__ __nv_bfloat16 sm[];
    const unsigned smb = smem_u32(sm);
    const int tid = threadIdx.x, lane = tid & 31, warp = tid >> 5;
    const int wm = warp >> 1, wn = warp & 1;
    const int m0 = blockIdx.y * 128, n0g = blockIdx.x * 64;

    float acc[2][4][4];
#pragma unroll
    for (int i = 0; i < 2; i++)
#pragma unroll
        for (int j = 0; j < 4; j++)
#pragma unroll
            for (int e = 0; e < 4; e++) acc[i][j][e] = 0.0f;

#define ISSUE(CC)                                                              \
    { int kc_ = (CC) * 32; unsigned sg_ = ((CC) % 3) * STG_H;                  \
      _Pragma("unroll") for (int i_ = 0; i_ < 2; i_++) {                       \
          int v_ = tid + i_ * 256, r_ = v_ >> 2, c4_ = v_ & 3;                 \
          cpasync16r(smb + (sg_ + r_ * 40 + c4_ * 8) * 2,                      \
                     Ahi + (size_t)(m0 + r_) * K + kc_ + c4_ * 8);             \
          cpasync16r(smb + (sg_ + 5120 + r_ * 40 + c4_ * 8) * 2,               \
                     Alo + (size_t)(m0 + r_) * K + kc_ + c4_ * 8);             \
      }                                                                        \
      { int r_ = tid >> 2, c4_ = tid & 3;                                      \
        cpasync16r(smb + (sg_ + 10240 + r_ * 40 + c4_ * 8) * 2,                \
                   Bhi + (size_t)(n0g + r_) * K + kc_ + c4_ * 8);              \
        cpasync16r(smb + (sg_ + 12800 + r_ * 40 + c4_ * 8) * 2,                \
                   Blo + (size_t)(n0g + r_) * K + kc_ + c4_ * 8);              \
      }                                                                        \
      asm volatile("cp.async.commit_group;"); }

    const int NCH = K / 32;
    ISSUE(0)
    ISSUE(1)
    ISSUE(2)
    for (int c = 0; c < NCH; c++) {
        if (c + 2 < NCH)      asm volatile("cp.async.wait_group 2;" ::: "memory");
        else if (c + 1 < NCH) asm volatile("cp.async.wait_group 1;" ::: "memory");
        else                  asm volatile("cp.async.wait_group 0;" ::: "memory");
        __syncthreads();
        const unsigned sg = (c % 3) * STG_H;
        const unsigned ah = smb + sg * 2;
        const unsigned al = smb + (sg + 5120) * 2;
        const unsigned wh = smb + (sg + 10240) * 2;
        const unsigned wl = smb + (sg + 12800) * 2;
        const int arow = wm * 32 + (lane & 7) + ((lane & 8) ? 8 : 0);
        const int acolx = (lane & 16) ? 8 : 0;
        const int brow = wn * 32 + (lane & 7);
        const int bcolx = (lane & 8) ? 8 : 0;
#pragma unroll
        for (int ks = 0; ks < 2; ks++) {
            u32 a_h[2][4], a_l[2][4], b_h[4][2], b_l[4][2];
#pragma unroll
            for (int mi = 0; mi < 2; mi++) {
                unsigned off = ((arow + mi * 16) * 40 + ks * 16 + acolx) * 2;
                LDSM4(a_h[mi], ah + off);
                LDSM4(a_l[mi], al + off);
            }
#pragma unroll
            for (int ni = 0; ni < 4; ni++) {
                unsigned off = ((brow + ni * 8) * 40 + ks * 16 + bcolx) * 2;
                LDSM2(b_h[ni], wh + off);
                LDSM2(b_l[ni], wl + off);
            }
#pragma unroll
            for (int mi = 0; mi < 2; mi++)
#pragma unroll
                for (int ni = 0; ni < 4; ni++) {
                    MMA16816(acc[mi][ni], a_h[mi], b_h[ni]);
                    MMA16816(acc[mi][ni], a_h[mi], b_l[ni]);
                    MMA16816(acc[mi][ni], a_l[mi], b_h[ni]);
                }
        }
        __syncthreads();
        if (c + 3 < NCH) ISSUE(c + 3)
    }
#undef ISSUE

    const int NCW = (CROW == 1) ? O_ : H_;
#pragma unroll
    for (int mi = 0; mi < 2; mi++) {
        int m = m0 + wm * 32 + mi * 16 + (lane >> 2);
        int mB = m + 8;
        size_t r0, r1;
        if (CROW == 1)      { r0 = (size_t)(m & 63) * S_ + (m >> 6);  r1 = (size_t)(mB & 63) * S_ + (mB >> 6); }
        else if (CROW == 2) { r0 = (size_t)(m % S_) * 64 + (m / S_);  r1 = (size_t)(mB % S_) * 64 + (mB / S_); }
        else                { r0 = (size_t)m;                          r1 = (size_t)mB; }
#pragma unroll
        for (int ni = 0; ni < 4; ni++) {
            int n = n0g + wn * 32 + ni * 8 + (lane & 3) * 2;
            float bv0 = __ldg(b1 + n) + (HASB2 ? __ldg(b2 + n) : 0.0f);
            float bv1 = __ldg(b1 + n + 1) + (HASB2 ? __ldg(b2 + n + 1) : 0.0f);
            *(float2*)(C + r0 * NCW + n) = make_float2(acc[mi][ni][0] + bv0, acc[mi][ni][1] + bv1);
            *(float2*)(C + r1 * NCW + n) = make_float2(acc[mi][ni][2] + bv0, acc[mi][ni][3] + bv1);
        }
    }
}

// Recurrence — R6 champion (unchanged).
#define SW_F  (H_ * 32)
#define SH_ROW 1028
#define SH_F  (16 * SH_ROW)
#define RED_U64 1024

__global__ void __launch_bounds__(512) rnn_layer_kernel(const float* __restrict__ Whh,
                                                        float* __restrict__ buf,
                                                        int* __restrict__ flags) {
    extern __shared__ __align__(16) float smem[];
    float* sW = smem;
    float* sH = smem + SW_F;
    u64* red = (u64*)(sH + SH_F);
    float* sPre = (float*)(red + 2 * RED_U64);

    const int tid = threadIdx.x;
    const int warp = tid >> 5, lane = tid & 31;
    const int ng4 = warp & 3, kg = warp >> 2;
    const int ks = lane & 7, q = lane >> 3;
    const int bg = blockIdx.x & 3;
    const int n0 = (blockIdx.x >> 2) * 32;
    const int b0 = bg * 16;
    const int ca = (((ng4 * 2) ^ ks) << 2), cb = ca ^ 4;
    const int mychunk = n0 >> 8;
    const int gtid = tid & 127;

#pragma unroll
    for (int i = 0; i < 16; i++) {
        int v = tid + i * 512;
        int j = v >> 8, k4 = v & 255;
        float4 f = __ldg((const float4*)(Whh + (size_t)(n0 + j) * H_ + k4 * 4));
        int sw = (((j >> 2) ^ (k4 & 7)) << 2) + (j & 3);
        sW[(k4 * 4 + 0) * 32 + sw] = f.x;
        sW[(k4 * 4 + 1) * 32 + sw] = f.y;
        sW[(k4 * 4 + 2) * 32 + sw] = f.z;
        sW[(k4 * 4 + 3) * 32 + sw] = f.w;
    }

    if (lane < 16) {
        float* addr = buf + ((size_t)(b0 + warp)) * H_ + n0 + lane * 2;
        float2 v = unpk(*(const u64*)addr);
        *(u64*)addr = pack2(tanhf(v.x), tanhf(v.y));
    }
    __syncwarp();
    if (lane == 0) red_release(&flags[0 * 16 + bg * 4 + mychunk]);
    __syncthreads();

    const float* hb0 = sH + (0 * 4 + q) * SH_ROW + kg * 256 + ks * 4;
    const float* hb1 = sH + (1 * 4 + q) * SH_ROW + kg * 256 + ks * 4;
    const float* hb2 = sH + (2 * 4 + q) * SH_ROW + kg * 256 + ks * 4;
    const float* hb3 = sH + (3 * 4 + q) * SH_ROW + kg * 256 + ks * 4;
    const float* wbase = sW + (size_t)(kg * 256 + ks * 4) * 32;

    for (int t = 1; t < S_; t++) {
        u64* redw = red + (t & 1) * RED_U64;
        float* sPw = sPre + (t & 1) * 512;

        if (gtid < 32) {
            int r = kg * 4 + (gtid >> 3), c = (gtid & 7) * 4;
            cpasync16(&sPw[r * 32 + c], buf + ((size_t)t * B_ + b0 + r) * H_ + n0 + c);
        }
        if (gtid == 0) {
            const int* fl = &flags[(t - 1) * 16 + bg * 4 + kg];
            while (ld_acq(fl) < 128) { }
        }
        asm volatile("bar.sync %0, 128;" :: "r"(1 + kg) : "memory");
        {
            const float* src = buf + ((size_t)(t - 1) * B_ + b0) * H_ + kg * 256;
#pragma unroll
            for (int i = 0; i < 8; i++) {
                int v = gtid + i * 128;
                int r = v >> 6, c = v & 63;
                cpasync16(&sH[r * SH_ROW + kg * 256 + c * 4], src + (size_t)r * H_ + c * 4);
            }
            asm volatile("cp.async.wait_all;" ::: "memory");
            asm volatile("bar.sync %0, 128;" :: "r"(1 + kg) : "memory");
        }

        u64 acc[4][4];
#pragma unroll
        for (int i = 0; i < 4; i++)
#pragma unroll
            for (int j = 0; j < 4; j++) acc[i][j] = 0ull;

#pragma unroll
        for (int it = 0; it < 8; it++) {
            const int fo = it * 32;
            float4 h0 = *(const float4*)(hb0 + fo);
            float4 h1 = *(const float4*)(hb1 + fo);
            float4 h2 = *(const float4*)(hb2 + fo);
            float4 h3 = *(const float4*)(hb3 + fo);
            const float* wr = wbase + (size_t)fo * 32;
#define DO_KK(KK, CMP)                                                      \
            {                                                               \
                ulonglong2 wa = *(const ulonglong2*)(wr + KK * 32 + ca);    \
                ulonglong2 wb = *(const ulonglong2*)(wr + KK * 32 + cb);    \
                u64 p0 = pack2(h0.CMP, h0.CMP);                             \
                u64 p1 = pack2(h1.CMP, h1.CMP);                             \
                u64 p2 = pack2(h2.CMP, h2.CMP);                             \
                u64 p3 = pack2(h3.CMP, h3.CMP);                             \
                acc[0][0] = fma2(p0, wa.x, acc[0][0]);                      \
                acc[0][1] = fma2(p0, wa.y, acc[0][1]);                      \
                acc[0][2] = fma2(p0, wb.x, acc[0][2]);                      \
                acc[0][3] = fma2(p0, wb.y, acc[0][3]);                      \
                acc[1][0] = fma2(p1, wa.x, acc[1][0]);                      \
                acc[1][1] = fma2(p1, wa.y, acc[1][1]);                      \
                acc[1][2] = fma2(p1, wb.x, acc[1][2]);                      \
                acc[1][3] = fma2(p1, wb.y, acc[1][3]);                      \
                acc[2][0] = fma2(p2, wa.x, acc[2][0]);                      \
                acc[2][1] = fma2(p2, wa.y, acc[2][1]);                      \
                acc[2][2] = fma2(p2, wb.x, acc[2][2]);                      \
                acc[2][3] = fma2(p2, wb.y, acc[2][3]);                      \
                acc[3][0] = fma2(p3, wa.x, acc[3][0]);                      \
                acc[3][1] = fma2(p3, wa.y, acc[3][1]);                      \
                acc[3][2] = fma2(p3, wb.x, acc[3][2]);                      \
                acc[3][3] = fma2(p3, wb.y, acc[3][3]);                      \
            }
            DO_KK(0, x)
            DO_KK(1, y)
            DO_KK(2, z)
            DO_KK(3, w)
#undef DO_KK
        }

#pragma unroll
        for (int i = 0; i < 4; i++)
#pragma unroll
            for (int j = 0; j < 4; j++) {
                acc[i][j] = add2(acc[i][j], __shfl_xor_sync(0xffffffffu, acc[i][j], 1));
                acc[i][j] = add2(acc[i][j], __shfl_xor_sync(0xffffffffu, acc[i][j], 2));
                acc[i][j] = add2(acc[i][j], __shfl_xor_sync(0xffffffffu, acc[i][j], 4));
            }

        if (ks == 0) {
#pragma unroll
            for (int i = 0; i < 4; i++)
#pragma unroll
                for (int j = 0; j < 4; j++)
                    redw[(kg * 16 + (i * 4 + q)) * 16 + ng4 * 4 + j] = acc[i][j];
        }
        __syncthreads();

        if (lane < 16) {
            int b = warp, P = lane;
            u64 s01 = add2(redw[(0 * 16 + b) * 16 + P], redw[(1 * 16 + b) * 16 + P]);
            u64 s23 = add2(redw[(2 * 16 + b) * 16 + P], redw[(3 * 16 + b) * 16 + P]);
            u64 s = add2(s01, s23);
            s = add2(s, *(const u64*)&sPw[b * 32 + P * 2]);
            float2 v = unpk(s);
            *(u64*)(buf + ((size_t)t * B_ + b0 + b) * H_ + n0 + P * 2)
                = pack2(tanhf(v.x), tanhf(v.y));
        }
        __syncwarp();
        if (lane == 0) red_release(&flags[t * 16 + bg * 4 + mychunk]);
    }
}

extern "C" void kernel_launch(void* const* d_in, const int* in_sizes, int n_in,
                              void* d_out, int out_size) {
    const float* x      = (const float*)d_in[0];
    const float* W_ih_0 = (const float*)d_in[1];
    const float* W_hh_0 = (const float*)d_in[2];
    const float* b_ih_0 = (const float*)d_in[3];
    const float* b_hh_0 = (const float*)d_in[4];
    const float* W_ih_1 = (const float*)d_in[5];
    const float* W_hh_1 = (const float*)d_in[6];
    const float* b_ih_1 = (const float*)d_in[7];
    const float* b_hh_1 = (const float*)d_in[8];
    const float* fc_w   = (const float*)d_in[9];
    const float* fc_b   = (const float*)d_in[10];
    float* out = (float*)d_out;

    float *buf0, *buf1;
    int* flags;
    __nv_bfloat16 *ahi, *alo, *bhi, *blo;
    cudaGetSymbolAddress((void**)&buf0, g_buf0);
    cudaGetSymbolAddress((void**)&buf1, g_buf1);
    cudaGetSymbolAddress((void**)&flags, g_flags);
    cudaGetSymbolAddress((void**)&ahi, g_ahi);
    cudaGetSymbolAddress((void**)&alo, g_alo);
    cudaGetSymbolAddress((void**)&bhi, g_bhi);
    cudaGetSymbolAddress((void**)&blo, g_blo);

    const int rnn_smem = (SW_F + SH_F) * 4 + 2 * RED_U64 * 8 + 2 * 512 * 4;
    const int mg_smem  = 3 * STG_H * 2;   // 92160 B
    static bool attr_set = false;
    if (!attr_set) {
        cudaFuncSetAttribute(rnn_layer_kernel, cudaFuncAttributeMaxDynamicSharedMemorySize, rnn_smem);
        cudaFuncSetAttribute(mgemm_k<I_, 2, 1>, cudaFuncAttributeMaxDynamicSharedMemorySize, mg_smem);
        cudaFuncSetAttribute(mgemm_k<H_, 0, 1>, cudaFuncAttributeMaxDynamicSharedMemorySize, mg_smem);
        cudaFuncSetAttribute(mgemm_k<H_, 1, 0>, cudaFuncAttributeMaxDynamicSharedMemorySize, mg_smem);
        attr_set = true;
    }

    zero_flags_k<<<16, 1024>>>(flags);
    // pre0 via tensor cores: split x (m = b*S+s) and W_ih_0
    split_k<<<(B_ * S_ * I_ / 4) / 256, 256>>>(x, ahi, alo);
    split_k<<<(H_ * I_ / 4) / 256, 256>>>(W_ih_0, bhi, blo);
    mgemm_k<I_, 2, 1><<<dim3(H_ / 64, (B_ * S_) / 128), 256, mg_smem>>>(
        ahi, alo, bhi, blo, b_ih_0, b_hh_0, buf0);
    // L0 recurrence
    rnn_layer_kernel<<<128, 512, rnn_smem>>>(W_hh_0, buf0, flags);
    // pre1 via tensor cores
    split_k<<<(S_ * B_ * H_ / 4) / 256, 256>>>(buf0, ahi, alo);
    split_k<<<(H_ * H_ / 4) / 256, 256>>>(W_ih_1, bhi, blo);
    mgemm_k<H_, 0, 1><<<dim3(H_ / 64, (S_ * B_) / 128), 256, mg_smem>>>(
        ahi, alo, bhi, blo, b_ih_1, b_hh_1, buf1);
    // L1 recurrence
    rnn_layer_kernel<<<128, 512, rnn_smem>>>(W_hh_1, buf1, flags + S_ * 16);
    // fc via tensor cores
    split_k<<<(S_ * B_ * H_ / 4) / 256, 256>>>(buf1, ahi, alo);
    split_k<<<(O_ * H_ / 4) / 256, 256>>>(fc_w, bhi, blo);
    mgemm_k<H_, 1, 0><<<dim3(O_ / 64, (S_ * B_) / 128), 256, mg_smem>>>(
        ahi, alo, bhi, blo, fc_b, nullptr, out);
}

// round 15
// speedup vs baseline: 2.1058x; 1.6470x over previous
#include <cuda_runtime.h>
#include <cuda_bf16.h>
#include <math.h>

#define B_ 64
#define S_ 512
#define I_ 256
#define H_ 1024
#define O_ 256

__device__ float g_buf0[S_ * B_ * H_];
__device__ float g_buf1[S_ * B_ * H_];
__device__ int g_flags[2 * S_ * 16];
__device__ __nv_bfloat16 g_ahi[S_ * B_ * H_];   // h (or split A) hi
__device__ __nv_bfloat16 g_alo[S_ * B_ * H_];   // h (or split A) lo
__device__ __nv_bfloat16 g_bhi[H_ * H_];        // split W hi (gemm B)
__device__ __nv_bfloat16 g_blo[H_ * H_];
__device__ __nv_bfloat16 g_whi[H_ * H_];        // split W_hh hi (recurrence)
__device__ __nv_bfloat16 g_wlo[H_ * H_];

typedef unsigned long long u64;
typedef unsigned int u32;

__device__ __forceinline__ void cpasync16r(unsigned sdst, const void* gsrc) {
    asm volatile("cp.async.cg.shared.global [%0], [%1], 16;" :: "r"(sdst), "l"(gsrc));
}
__device__ __forceinline__ int ld_acq(const int* p) {
    int v; asm volatile("ld.acquire.gpu.global.b32 %0, [%1];" : "=r"(v) : "l"(p) : "memory");
    return v;
}
__device__ __forceinline__ void red_release(int* p) {
    asm volatile("red.release.gpu.global.add.s32 [%0], 1;" :: "l"(p) : "memory");
}
__device__ __forceinline__ unsigned smem_u32(const void* p) {
    unsigned a; asm("{ .reg .u64 t; cvta.to.shared.u64 t, %1; cvt.u32.u64 %0, t; }" : "=r"(a) : "l"(p));
    return a;
}
// split x into bf16 hi + lo, packed pair -> u32 each
__device__ __forceinline__ u32 splitpk(float x, float y, u32& lo) {
    __nv_bfloat16 hx = __float2bfloat16(x), hy = __float2bfloat16(y);
    __nv_bfloat16 lx = __float2bfloat16(x - __bfloat162float(hx));
    __nv_bfloat16 ly = __float2bfloat16(y - __bfloat162float(hy));
    lo = ((u32)__bfloat16_as_ushort(ly) << 16) | __bfloat16_as_ushort(lx);
    return ((u32)__bfloat16_as_ushort(hy) << 16) | __bfloat16_as_ushort(hx);
}

__global__ void zero_flags_k(int* f) { f[blockIdx.x * 1024 + threadIdx.x] = 0; }

__global__ void __launch_bounds__(256) split_k(const float* __restrict__ src,
                                               __nv_bfloat16* __restrict__ hi,
                                               __nv_bfloat16* __restrict__ lo) {
    int i = blockIdx.x * 256 + threadIdx.x;
    float4 v = __ldg((const float4*)src + i);
    u32 h0, h1, l0, l1;
    h0 = splitpk(v.x, v.y, l0);
    h1 = splitpk(v.z, v.w, l1);
    ((uint2*)hi)[i] = make_uint2(h0, h1);
    ((uint2*)lo)[i] = make_uint2(l0, l1);
}

// ---------------------------------------------------------------------------
// Split-bf16 mma.sync GEMM (validated R13/R14). 128x64 tile, 8 warps, 3-stage.
// CROW=0: row=m width H_; CROW=1: row=(m&63)*S_+(m>>6) width O_;
// CROW=2: row=(m%S_)*64+(m/S_) width H_.
// ---------------------------------------------------------------------------
#define LDSM4(R, ADDR) asm volatile( \
    "ldmatrix.sync.aligned.m8n8.x4.shared.b16 {%0,%1,%2,%3}, [%4];" \
    : "=r"((R)[0]), "=r"((R)[1]), "=r"((R)[2]), "=r"((R)[3]) : "r"(ADDR))
#define LDSM2(R, ADDR) asm volatile( \
    "ldmatrix.sync.aligned.m8n8.x2.shared.b16 {%0,%1}, [%2];" \
    : "=r"((R)[0]), "=r"((R)[1]) : "r"(ADDR))
#define MMA16816(D, A, Bv) asm volatile( \
    "mma.sync.aligned.m16n8k16.row.col.f32.bf16.bf16.f32 " \
    "{%0,%1,%2,%3}, {%4,%5,%6,%7}, {%8,%9}, {%0,%1,%2,%3};" \
    : "+f"((D)[0]), "+f"((D)[1]), "+f"((D)[2]), "+f"((D)[3]) \
    : "r"((A)[0]), "r"((A)[1]), "r"((A)[2]), "r"((A)[3]), "r"((Bv)[0]), "r"((Bv)[1]))

#define STG_H 15360

template <int K, int CROW, int HASB2>
__global__ void __launch_bounds__(256) mgemm_k(const __nv_bfloat16* __restrict__ Ahi,
                                               const __nv_bfloat16* __restrict__ Alo,
                                               const __nv_bfloat16* __restrict__ Bhi,
                                               const __nv_bfloat16* __restrict__ Blo,
                                               const float* __restrict__ b1,
                                               const float* __restrict__ b2,
                                               float* __restrict__ C) {
    extern __shared__ __nv_bfloat16 sm[];
    const unsigned smb = smem_u32(sm);
    const int tid = threadIdx.x, lane = tid & 31, warp = tid >> 5;
    const int wm = warp >> 1, wn = warp & 1;
    const int m0 = blockIdx.y * 128, n0g = blockIdx.x * 64;

    float acc[2][4][4];
#pragma unroll
    for (int i = 0; i < 2; i++)
#pragma unroll
        for (int j = 0; j < 4; j++)
#pragma unroll
            for (int e = 0; e < 4; e++) acc[i][j][e] = 0.0f;

#define ISSUE(CC)                                                              \
    { int kc_ = (CC) * 32; unsigned sg_ = ((CC) % 3) * STG_H;                  \
      _Pragma("unroll") for (int i_ = 0; i_ < 2; i_++) {                       \
          int v_ = tid + i_ * 256, r_ = v_ >> 2, c4_ = v_ & 3;                 \
          cpasync16r(smb + (sg_ + r_ * 40 + c4_ * 8) * 2,                      \
                     Ahi + (size_t)(m0 + r_) * K + kc_ + c4_ * 8);             \
          cpasync16r(smb + (sg_ + 5120 + r_ * 40 + c4_ * 8) * 2,               \
                     Alo + (size_t)(m0 + r_) * K + kc_ + c4_ * 8);             \
      }                                                                        \
      { int r_ = tid >> 2, c4_ = tid & 3;                                      \
        cpasync16r(smb + (sg_ + 10240 + r_ * 40 + c4_ * 8) * 2,                \
                   Bhi + (size_t)(n0g + r_) * K + kc_ + c4_ * 8);              \
        cpasync16r(smb + (sg_ + 12800 + r_ * 40 + c4_ * 8) * 2,                \
                   Blo + (size_t)(n0g + r_) * K + kc_ + c4_ * 8);              \
      }                                                                        \
      asm volatile("cp.async.commit_group;"); }

    const int NCH = K / 32;
    ISSUE(0)
    ISSUE(1)
    ISSUE(2)
    for (int c = 0; c < NCH; c++) {
        if (c + 2 < NCH)      asm volatile("cp.async.wait_group 2;" ::: "memory");
        else if (c + 1 < NCH) asm volatile("cp.async.wait_group 1;" ::: "memory");
        else                  asm volatile("cp.async.wait_group 0;" ::: "memory");
        __syncthreads();
        const unsigned sg = (c % 3) * STG_H;
        const unsigned ah = smb + sg * 2;
        const unsigned al = smb + (sg + 5120) * 2;
        const unsigned wh = smb + (sg + 10240) * 2;
        const unsigned wl = smb + (sg + 12800) * 2;
        const int arow = wm * 32 + (lane & 7) + ((lane & 8) ? 8 : 0);
        const int acolx = (lane & 16) ? 8 : 0;
        const int brow = wn * 32 + (lane & 7);
        const int bcolx = (lane & 8) ? 8 : 0;
#pragma unroll
        for (int ks = 0; ks < 2; ks++) {
            u32 a_h[2][4], a_l[2][4], b_h[4][2], b_l[4][2];
#pragma unroll
            for (int mi = 0; mi < 2; mi++) {
                unsigned off = ((arow + mi * 16) * 40 + ks * 16 + acolx) * 2;
                LDSM4(a_h[mi], ah + off);
                LDSM4(a_l[mi], al + off);
            }
#pragma unroll
            for (int ni = 0; ni < 4; ni++) {
                unsigned off = ((brow + ni * 8) * 40 + ks * 16 + bcolx) * 2;
                LDSM2(b_h[ni], wh + off);
                LDSM2(b_l[ni], wl + off);
            }
#pragma unroll
            for (int mi = 0; mi < 2; mi++)
#pragma unroll
                for (int ni = 0; ni < 4; ni++) {
                    MMA16816(acc[mi][ni], a_h[mi], b_h[ni]);
                    MMA16816(acc[mi][ni], a_h[mi], b_l[ni]);
                    MMA16816(acc[mi][ni], a_l[mi], b_h[ni]);
                }
        }
        __syncthreads();
        if (c + 3 < NCH) ISSUE(c + 3)
    }
#undef ISSUE

    const int NCW = (CROW == 1) ? O_ : H_;
#pragma unroll
    for (int mi = 0; mi < 2; mi++) {
        int m = m0 + wm * 32 + mi * 16 + (lane >> 2);
        int mB = m + 8;
        size_t r0, r1;
        if (CROW == 1)      { r0 = (size_t)(m & 63) * S_ + (m >> 6);  r1 = (size_t)(mB & 63) * S_ + (mB >> 6); }
        else if (CROW == 2) { r0 = (size_t)(m % S_) * 64 + (m / S_);  r1 = (size_t)(mB % S_) * 64 + (mB / S_); }
        else                { r0 = (size_t)m;                          r1 = (size_t)mB; }
#pragma unroll
        for (int ni = 0; ni < 4; ni++) {
            int n = n0g + wn * 32 + ni * 8 + (lane & 3) * 2;
            float bv0 = __ldg(b1 + n) + (HASB2 ? __ldg(b2 + n) : 0.0f);
            float bv1 = __ldg(b1 + n + 1) + (HASB2 ? __ldg(b2 + n + 1) : 0.0f);
            *(float2*)(C + r0 * NCW + n) = make_float2(acc[mi][ni][0] + bv0, acc[mi][ni][1] + bv1);
            *(float2*)(C + r1 * NCW + n) = make_float2(acc[mi][ni][2] + bv0, acc[mi][ni][3] + bv1);
        }
    }
}

// ---------------------------------------------------------------------------
// Tensor-core recurrence. grid 128 = 32 ng x 4 bg; CTA = 32 n x 16 b.
// 256 thr = 8 warps: warp = kg*2 + wn; kg owns k-chunk of 256, wn n-half 16.
// W_hh hi/lo slices resident in smem (rows, stride 1032 halves = odd*16B).
// h kept as bf16 hi/lo in Hhi/Hlo ([s][b][h]); pre read fp32 from buf.
// Per step: pre-prefetch; per-kg poll(target 64) + copy h chunk (hi+lo);
// mma compute (3 split terms); kg-partials in smem; finalize = sum + pre +
// tanh + re-split + u32 stores; per-warp release.
// ---------------------------------------------------------------------------
#define oWloB 66048u
#define oHhiB 132096u
#define oHloB 165120u
#define oRedB 198144u
#define oPreB 216576u
#define RNN_SMEM 220672

__global__ void __launch_bounds__(256) rnn_mma_k(const __nv_bfloat16* __restrict__ Whi,
                                                 const __nv_bfloat16* __restrict__ Wlo,
                                                 const float* __restrict__ pre,
                                                 __nv_bfloat16* Hhi,
                                                 __nv_bfloat16* Hlo,
                                                 int* __restrict__ flags) {
    extern __shared__ __align__(16) char sch[];
    const unsigned smb = smem_u32(sch);
    const int tid = threadIdx.x, lane = tid & 31, warp = tid >> 5;
    const int wn = warp & 1, kg = warp >> 1;
    const int bg = blockIdx.x & 3, ng = blockIdx.x >> 2;
    const int n0 = ng * 32, b0 = bg * 16;
    const int mychunk = ng >> 3;
    const int gtid = tid & 63;

    // Load W slice (rows with 1032-half stride)
    for (int i = tid; i < 32 * 128; i += 256) {
        int r = i >> 7, c = i & 127;
        cpasync16r(smb + (r * 1032 + c * 8) * 2, Whi + (size_t)(n0 + r) * H_ + c * 8);
        cpasync16r(smb + oWloB + (r * 1032 + c * 8) * 2, Wlo + (size_t)(n0 + r) * H_ + c * 8);
    }
    asm volatile("cp.async.wait_all;" ::: "memory");

    // t = 0: h_0 = tanh(pre_0), split-stored
    {
        int b = tid >> 4, P = tid & 15;
        float2 v = *(const float2*)(pre + ((size_t)(b0 + b)) * H_ + n0 + P * 2);
        u32 lo, hi = splitpk(tanhf(v.x), tanhf(v.y), lo);
        size_t o = ((size_t)(b0 + b)) * H_ + n0 + P * 2;
        *(u32*)(Hhi + o) = hi;
        *(u32*)(Hlo + o) = lo;
    }
    __syncwarp();
    if (lane == 0) red_release(&flags[0 * 16 + bg * 4 + mychunk]);
    __syncthreads();

    const int arow = (lane & 7) + ((lane & 8) ? 8 : 0);
    const int acol = (lane & 16) ? 8 : 0;
    const int brow = wn * 16 + (lane & 7);
    const int bcol = (lane & 8) ? 8 : 0;

    for (int t = 1; t < S_; t++) {
        float* redw = (float*)(sch + oRedB + (t & 1) * 9216);
        float* sPw  = (float*)(sch + oPreB + (t & 1) * 2048);

        // prefetch pre_t tile (512 floats)
        if (tid < 128) {
            int r = tid >> 3, c = (tid & 7) * 4;
            cpasync16r(smb + oPreB + (t & 1) * 2048 + (r * 32 + c) * 4,
                       pre + ((size_t)t * B_ + b0 + r) * H_ + n0 + c);
        }
        // poll own chunk
        if (gtid == 0) {
            const int* fl = &flags[(t - 1) * 16 + bg * 4 + kg];
            while (ld_acq(fl) < 64) { }
        }
        asm volatile("bar.sync %0, 64;" :: "r"(1 + kg) : "memory");
        // copy h chunk kg (hi+lo): 16 rows x 512B each half
        {
            const __nv_bfloat16* sh_ = Hhi + ((size_t)(t - 1) * B_ + b0) * H_ + kg * 256;
            const __nv_bfloat16* sl_ = Hlo + ((size_t)(t - 1) * B_ + b0) * H_ + kg * 256;
#pragma unroll
            for (int i = 0; i < 8; i++) {
                int v = gtid + i * 64, r = v >> 5, c = v & 31;
                unsigned so = ((r * 1032 + kg * 256 + c * 8)) * 2;
                cpasync16r(smb + oHhiB + so, sh_ + (size_t)r * H_ + c * 8);
                cpasync16r(smb + oHloB + so, sl_ + (size_t)r * H_ + c * 8);
            }
            asm volatile("cp.async.wait_all;" ::: "memory");
            asm volatile("bar.sync %0, 64;" :: "r"(1 + kg) : "memory");
        }

        // compute: 16b x 16n x 256k per warp, 3 split terms
        float c0[4] = {0, 0, 0, 0}, c1[4] = {0, 0, 0, 0};
#pragma unroll
        for (int ks = 0; ks < 16; ks++) {
            const int kk = kg * 256 + ks * 16;
            u32 ah[4], al[4], bh[2], bl[2];
            unsigned aoff = (arow * 1032 + kk + acol) * 2;
            LDSM4(ah, smb + oHhiB + aoff);
            LDSM4(al, smb + oHloB + aoff);
            unsigned wb0 = smb + (brow * 1032 + kk + bcol) * 2;
            LDSM2(bh, wb0);
            LDSM2(bl, wb0 + oWloB);
            MMA16816(c0, ah, bh);
            MMA16816(c0, ah, bl);
            MMA16816(c0, al, bh);
            unsigned wb1 = wb0 + 8 * 1032 * 2;
            LDSM2(bh, wb1);
            LDSM2(bl, wb1 + oWloB);
            MMA16816(c1, ah, bh);
            MMA16816(c1, ah, bl);
            MMA16816(c1, al, bh);
        }
        // write kg-partials: red[kg][b(16)][36]
        {
            int rb = lane >> 2, nb = wn * 16 + (lane & 3) * 2;
#pragma unroll
            for (int e = 0; e < 4; e++) {
                int b = rb + ((e >= 2) ? 8 : 0);
                int n = nb + (e & 1);
                redw[(kg * 16 + b) * 36 + n] = c0[e];
                redw[(kg * 16 + b) * 36 + n + 8] = c1[e];
            }
        }
        __syncthreads();

        // finalize: thread -> (b, n-pair)
        {
            int b = tid >> 4, P = tid & 15;
            float sx = 0.f, sy = 0.f;
#pragma unroll
            for (int g = 0; g < 4; g++) {
                sx += redw[(g * 16 + b) * 36 + P * 2];
                sy += redw[(g * 16 + b) * 36 + P * 2 + 1];
            }
            float2 pv = *(const float2*)(sPw + b * 32 + P * 2);
            u32 lo, hi = splitpk(tanhf(sx + pv.x), tanhf(sy + pv.y), lo);
            size_t o = ((size_t)t * B_ + b0 + b) * H_ + n0 + P * 2;
            *(u32*)(Hhi + o) = hi;
            *(u32*)(Hlo + o) = lo;
        }
        __syncwarp();
        if (lane == 0) red_release(&flags[t * 16 + bg * 4 + mychunk]);
    }
}

// ---------------------------------------------------------------------------

extern "C" void kernel_launch(void* const* d_in, const int* in_sizes, int n_in,
                              void* d_out, int out_size) {
    const float* x      = (const float*)d_in[0];
    const float* W_ih_0 = (const float*)d_in[1];
    const float* W_hh_0 = (const float*)d_in[2];
    const float* b_ih_0 = (const float*)d_in[3];
    const float* b_hh_0 = (const float*)d_in[4];
    const float* W_ih_1 = (const float*)d_in[5];
    const float* W_hh_1 = (const float*)d_in[6];
    const float* b_ih_1 = (const float*)d_in[7];
    const float* b_hh_1 = (const float*)d_in[8];
    const float* fc_w   = (const float*)d_in[9];
    const float* fc_b   = (const float*)d_in[10];
    float* out = (float*)d_out;

    float *buf0, *buf1;
    int* flags;
    __nv_bfloat16 *ahi, *alo, *bhi, *blo, *whi, *wlo;
    cudaGetSymbolAddress((void**)&buf0, g_buf0);
    cudaGetSymbolAddress((void**)&buf1, g_buf1);
    cudaGetSymbolAddress((void**)&flags, g_flags);
    cudaGetSymbolAddress((void**)&ahi, g_ahi);
    cudaGetSymbolAddress((void**)&alo, g_alo);
    cudaGetSymbolAddress((void**)&bhi, g_bhi);
    cudaGetSymbolAddress((void**)&blo, g_blo);
    cudaGetSymbolAddress((void**)&whi, g_whi);
    cudaGetSymbolAddress((void**)&wlo, g_wlo);

    const int mg_smem = 3 * STG_H * 2;   // 92160 B
    static bool attr_set = false;
    if (!attr_set) {
        cudaFuncSetAttribute(rnn_mma_k, cudaFuncAttributeMaxDynamicSharedMemorySize, RNN_SMEM);
        cudaFuncSetAttribute(mgemm_k<I_, 2, 1>, cudaFuncAttributeMaxDynamicSharedMemorySize, mg_smem);
        cudaFuncSetAttribute(mgemm_k<H_, 0, 1>, cudaFuncAttributeMaxDynamicSharedMemorySize, mg_smem);
        cudaFuncSetAttribute(mgemm_k<H_, 1, 0>, cudaFuncAttributeMaxDynamicSharedMemorySize, mg_smem);
        attr_set = true;
    }

    zero_flags_k<<<16, 1024>>>(flags);
    // pre0: split x and W_ih_0, tensor GEMM into buf0 [s][b][h]
    split_k<<<(B_ * S_ * I_ / 4) / 256, 256>>>(x, ahi, alo);
    split_k<<<(H_ * I_ / 4) / 256, 256>>>(W_ih_0, bhi, blo);
    mgemm_k<I_, 2, 1><<<dim3(H_ / 64, (B_ * S_) / 128), 256, mg_smem>>>(
        ahi, alo, bhi, blo, b_ih_0, b_hh_0, buf0);
    // L0 recurrence (writes h0 hi/lo into ahi/alo)
    split_k<<<(H_ * H_ / 4) / 256, 256>>>(W_hh_0, whi, wlo);
    rnn_mma_k<<<128, 256, RNN_SMEM>>>(whi, wlo, buf0, ahi, alo, flags);
    // pre1 = h0 @ W1_ih^T + biases (h0 already split)
    split_k<<<(H_ * H_ / 4) / 256, 256>>>(W_ih_1, bhi, blo);
    mgemm_k<H_, 0, 1><<<dim3(H_ / 64, (S_ * B_) / 128), 256, mg_smem>>>(
        ahi, alo, bhi, blo, b_ih_1, b_hh_1, buf1);
    // L1 recurrence (writes h1 hi/lo into ahi/alo)
    split_k<<<(H_ * H_ / 4) / 256, 256>>>(W_hh_1, whi, wlo);
    rnn_mma_k<<<128, 256, RNN_SMEM>>>(whi, wlo, buf1, ahi, alo, flags + S_ * 16);
    // fc (h1 already split)
    split_k<<<(O_ * H_ / 4) / 256, 256>>>(fc_w, bhi, blo);
    mgemm_k<H_, 1, 0><<<dim3(O_ / 64, (S_ * B_) / 128), 256, mg_smem>>>(
        ahi, alo, bhi, blo, fc_b, nullptr, out);
}